// round 1
// baseline (speedup 1.0000x reference)
#include <cuda_runtime.h>

#define NHh 8
#define KDh 32
#define Dm 256          // NH*HD
#define OC 1280         // NH*(4*KD+HD)
#define HW 4096
#define NB 2
#define SCALEF 0.17677669529663687f

// Scratch (device globals; no runtime allocation allowed)
__device__ float P_g[NB * OC * HW];            // [b][o][hw]   (42 MB)
__device__ float R_g[NB * NHh * 64 * HW];      // [b][H][i][hw] (row softmax, i = softmax axis)
__device__ float C_g[NB * NHh * 64 * HW];      // [b][H][i][hw] (col softmax, i = softmax axis)

// ---------------------------------------------------------------------------
// Kernel 1: projection GEMM  P[b,o,s] = sum_c W[o,c] * X[b,c,s]
// grid (N/64=64, M/64=20, B=2), 256 threads, 4x4 register tile, K-tile 16
// ---------------------------------------------------------------------------
__global__ void proj_kernel(const float* __restrict__ x, const float* __restrict__ w)
{
    int b  = blockIdx.z;
    int m0 = blockIdx.y * 64;
    int n0 = blockIdx.x * 64;
    int tid = threadIdx.x;

    __shared__ float a_s[16][68];   // [c][o]
    __shared__ float b_s[16][64];   // [c][s]

    float acc[4][4] = {};
    int tm = (tid >> 4) * 4;        // 0..60
    int tn = (tid & 15) * 4;        // 0..60
    const float* xb = x + b * (Dm * HW);

    for (int k0 = 0; k0 < Dm; k0 += 16) {
        // A tile: W[m0+o][k0 + c4*4 .. +3], o = tid/4
        {
            int o  = tid >> 2;
            int c4 = (tid & 3) * 4;
            float4 v = *(const float4*)&w[(m0 + o) * Dm + k0 + c4];
            a_s[c4 + 0][o] = v.x; a_s[c4 + 1][o] = v.y;
            a_s[c4 + 2][o] = v.z; a_s[c4 + 3][o] = v.w;
        }
        // B tile: X[b][k0+c][n0 + s4*4 .. +3], c = tid/16
        {
            int c  = tid >> 4;
            int s4 = (tid & 15) * 4;
            *(float4*)&b_s[c][s4] = *(const float4*)&xb[(k0 + c) * HW + n0 + s4];
        }
        __syncthreads();
        #pragma unroll
        for (int kc = 0; kc < 16; kc++) {
            float4 av = *(const float4*)&a_s[kc][tm];
            float4 bv = *(const float4*)&b_s[kc][tn];
            float avv[4] = {av.x, av.y, av.z, av.w};
            float bvv[4] = {bv.x, bv.y, bv.z, bv.w};
            #pragma unroll
            for (int i2 = 0; i2 < 4; i2++)
                #pragma unroll
                for (int j2 = 0; j2 < 4; j2++)
                    acc[i2][j2] += avv[i2] * bvv[j2];
        }
        __syncthreads();
    }

    float* pb = P_g + b * (OC * HW);
    #pragma unroll
    for (int i2 = 0; i2 < 4; i2++) {
        *(float4*)&pb[(m0 + tm + i2) * HW + n0 + tn] =
            make_float4(acc[i2][0], acc[i2][1], acc[i2][2], acc[i2][3]);
    }
}

// ---------------------------------------------------------------------------
// Kernel 2: row attention.  For fixed (b,H,w):
//   A[i,j] = SCALE * sum_d rq[d,i,w]*rk[d,j,w]; softmax over i per column j;
//   store R_g[bh][i][j*64 + w]   (hw = h*64+w with h == j)
// grid (64 w, 16 bh), 256 threads
// ---------------------------------------------------------------------------
__global__ void row_attn_kernel()
{
    int w  = blockIdx.x;
    int bh = blockIdx.y;
    int b  = bh >> 3, H = bh & 7;
    const float* base = P_g + (b * OC + H * 160) * HW;
    int tid = threadIdx.x;

    __shared__ float q_s[32][64];   // [d][i]
    __shared__ float k_s[32][64];
    __shared__ float a_s[64][68];

    for (int f = tid; f < 2048; f += 256) {
        int d = f >> 6, i = f & 63;
        q_s[d][i] = base[(0  + d) * HW + i * 64 + w];
        k_s[d][i] = base[(32 + d) * HW + i * 64 + w];
    }
    __syncthreads();

    int ti = (tid >> 4) * 4;
    int tj = (tid & 15) * 4;
    float acc[4][4] = {};
    #pragma unroll
    for (int d = 0; d < 32; d++) {
        float4 av = *(const float4*)&q_s[d][ti];
        float4 bv = *(const float4*)&k_s[d][tj];
        float avv[4] = {av.x, av.y, av.z, av.w};
        float bvv[4] = {bv.x, bv.y, bv.z, bv.w};
        #pragma unroll
        for (int u = 0; u < 4; u++)
            #pragma unroll
            for (int v2 = 0; v2 < 4; v2++)
                acc[u][v2] += avv[u] * bvv[v2];
    }
    #pragma unroll
    for (int u = 0; u < 4; u++)
        #pragma unroll
        for (int v2 = 0; v2 < 4; v2++)
            a_s[ti + u][tj + v2] = acc[u][v2] * SCALEF;
    __syncthreads();

    if (tid < 64) {
        int j = tid;
        float mx = -1e30f;
        #pragma unroll 8
        for (int i = 0; i < 64; i++) mx = fmaxf(mx, a_s[i][j]);
        float s = 0.f;
        #pragma unroll 8
        for (int i = 0; i < 64; i++) {
            float e = __expf(a_s[i][j] - mx);
            a_s[i][j] = e;
            s += e;
        }
        float inv = 1.f / s;
        float* rb = R_g + bh * (64 * HW);
        #pragma unroll 8
        for (int i = 0; i < 64; i++)
            rb[i * HW + j * 64 + w] = a_s[i][j] * inv;
    }
}

// ---------------------------------------------------------------------------
// Kernel 3: column attention.  For fixed (b,H,h):
//   A[i,j] = SCALE * sum_d cq[d,h,i]*ck[d,h,j]; softmax over i per column j;
//   store C_g[bh][i][h*64 + j]
// grid (64 h, 16 bh), 256 threads
// ---------------------------------------------------------------------------
__global__ void col_attn_kernel()
{
    int h  = blockIdx.x;
    int bh = blockIdx.y;
    int b  = bh >> 3, H = bh & 7;
    const float* base = P_g + (b * OC + H * 160) * HW;
    int tid = threadIdx.x;

    __shared__ float q_s[32][64];
    __shared__ float k_s[32][64];
    __shared__ float a_s[64][68];

    for (int f = tid; f < 2048; f += 256) {
        int d = f >> 6, i = f & 63;
        q_s[d][i] = base[(64 + d) * HW + h * 64 + i];
        k_s[d][i] = base[(96 + d) * HW + h * 64 + i];
    }
    __syncthreads();

    int ti = (tid >> 4) * 4;
    int tj = (tid & 15) * 4;
    float acc[4][4] = {};
    #pragma unroll
    for (int d = 0; d < 32; d++) {
        float4 av = *(const float4*)&q_s[d][ti];
        float4 bv = *(const float4*)&k_s[d][tj];
        float avv[4] = {av.x, av.y, av.z, av.w};
        float bvv[4] = {bv.x, bv.y, bv.z, bv.w};
        #pragma unroll
        for (int u = 0; u < 4; u++)
            #pragma unroll
            for (int v2 = 0; v2 < 4; v2++)
                acc[u][v2] += avv[u] * bvv[v2];
    }
    #pragma unroll
    for (int u = 0; u < 4; u++)
        #pragma unroll
        for (int v2 = 0; v2 < 4; v2++)
            a_s[ti + u][tj + v2] = acc[u][v2] * SCALEF;
    __syncthreads();

    if (tid < 64) {
        int j = tid;
        float mx = -1e30f;
        #pragma unroll 8
        for (int i = 0; i < 64; i++) mx = fmaxf(mx, a_s[i][j]);
        float s = 0.f;
        #pragma unroll 8
        for (int i = 0; i < 64; i++) {
            float e = __expf(a_s[i][j] - mx);
            a_s[i][j] = e;
            s += e;
        }
        float inv = 1.f / s;
        float* cb = C_g + bh * (64 * HW);
        #pragma unroll 8
        for (int i = 0; i < 64; i++)
            cb[i * HW + h * 64 + j] = a_s[i][j] * inv;
    }
}

// ---------------------------------------------------------------------------
// Kernel 4: fused output.
//   out[d,hw] = v[d,hw] + sum_i r[i,hw] * sum_j V[d,i,j] * c[j,hw]
// grid (HW/128=32, 16 bh), 256 threads; per-thread tile 4d x 4hw.
// c tile in smem [j][hw]; V panel for current i in smem [d][j]; r via L1.
// ---------------------------------------------------------------------------
__global__ void fused_out_kernel(float* __restrict__ out)
{
    int hw0 = blockIdx.x * 128;
    int bh  = blockIdx.y;
    int b   = bh >> 3, H = bh & 7;
    const float* vbase = P_g + (b * OC + H * 160 + 128) * HW;   // v slice [d][hw]
    const float* rbase = R_g + bh * (64 * HW);
    const float* cbase = C_g + bh * (64 * HW);
    int tid = threadIdx.x;

    __shared__ float c_s[64][128];   // [j][hw_local]  32 KB
    __shared__ float v_s[32][64];    // [d][j]          8 KB

    // load c tile: 8192 floats = 2048 float4
    for (int f = tid; f < 2048; f += 256) {
        int row  = f >> 5;            // 0..63
        int col4 = (f & 31) * 4;      // 0..124
        *(float4*)&c_s[row][col4] = *(const float4*)&cbase[row * HW + hw0 + col4];
    }

    int td = (tid >> 5) * 4;          // 0..28   (d tile)
    int tw = (tid & 31) * 4;          // 0..124  (hw tile)
    float acc[4][4] = {};             // [dd][ww]

    for (int i = 0; i < 64; i++) {
        __syncthreads();              // previous v_s fully consumed (and c_s ready on i==0)
        // load V panel for this i: V[d][j] = vbase[d*HW + i*64 + j], 2048 floats
        #pragma unroll
        for (int q = 0; q < 2; q++) {
            int f  = tid + q * 256;
            int dr = f >> 4;          // 0..31
            int c4 = (f & 15) * 4;    // 0..60
            *(float4*)&v_s[dr][c4] = *(const float4*)&vbase[dr * HW + i * 64 + c4];
        }
        __syncthreads();

        float4 rr = __ldg((const float4*)&rbase[i * HW + hw0 + tw]);
        float rrv[4] = {rr.x, rr.y, rr.z, rr.w};

        #pragma unroll 16
        for (int j = 0; j < 64; j++) {
            float4 cv = *(const float4*)&c_s[j][tw];
            float rc[4] = {rrv[0] * cv.x, rrv[1] * cv.y, rrv[2] * cv.z, rrv[3] * cv.w};
            float va[4] = {v_s[td][j], v_s[td + 1][j], v_s[td + 2][j], v_s[td + 3][j]};
            #pragma unroll
            for (int dd = 0; dd < 4; dd++)
                #pragma unroll
                for (int ww = 0; ww < 4; ww++)
                    acc[dd][ww] += va[dd] * rc[ww];
        }
    }

    // epilogue: + v, write out.  out channel = H*32 + d
    float* obase = out + (b * 256 + H * 32) * HW;
    #pragma unroll
    for (int dd = 0; dd < 4; dd++) {
        float4 vv = *(const float4*)&vbase[(td + dd) * HW + hw0 + tw];
        float4 res = make_float4(acc[dd][0] + vv.x, acc[dd][1] + vv.y,
                                 acc[dd][2] + vv.z, acc[dd][3] + vv.w);
        *(float4*)&obase[(td + dd) * HW + hw0 + tw] = res;
    }
}

// ---------------------------------------------------------------------------
extern "C" void kernel_launch(void* const* d_in, const int* in_sizes, int n_in,
                              void* d_out, int out_size)
{
    const float* x = (const float*)d_in[0];
    const float* w = (const float*)d_in[1];
    // defensive: identify by size (x = 2*256*64*64 = 2097152, w = 1280*256 = 327680)
    if (n_in >= 2 && in_sizes[0] == 327680 && in_sizes[1] == 2097152) {
        const float* t = x; x = w; w = t;
    }
    float* out = (float*)d_out;

    dim3 g1(64, 20, 2);
    proj_kernel<<<g1, 256>>>(x, w);

    dim3 g2(64, 16);
    row_attn_kernel<<<g2, 256>>>();
    col_attn_kernel<<<g2, 256>>>();

    dim3 g4(32, 16);
    fused_out_kernel<<<g4, 256>>>(out);
}

// round 4
// speedup vs baseline: 2.5483x; 2.5483x over previous
#include <cuda_runtime.h>
#include <cstdint>

#define NHh 8
#define Dm 256          // NH*HD
#define OC 1280         // NH*(4*KD+HD)
#define HW 4096
#define NB 2
#define SCALEF 0.17677669529663687f

// Scratch (device globals; no runtime allocation allowed)
__device__ float P_g[NB * OC * HW];            // [b][o][hw]
__device__ float R_g[NB * NHh * 64 * HW];      // [b][H][i][hw] row softmax
__device__ float C_g[NB * NHh * 64 * HW];      // [b][H][j][hw] col softmax

// ---------------------------------------------------------------------------
// helpers: tf32 rounding + mma.sync (sm_80+ PTX, works on plain sm_103 target)
// ---------------------------------------------------------------------------
__device__ __forceinline__ uint32_t f2tf32(float x) {
    uint32_t u;
    asm("cvt.rna.tf32.f32 %0, %1;" : "=r"(u) : "f"(x));
    return u;
}
__device__ __forceinline__ float f2tf32f(float x) {
    uint32_t u = f2tf32(x);
    return __uint_as_float(u);
}
__device__ __forceinline__ void mma16n8k8(float* d, const uint32_t* a,
                                          uint32_t b0, uint32_t b1) {
    asm volatile("mma.sync.aligned.m16n8k8.row.col.f32.tf32.tf32.f32 "
                 "{%0,%1,%2,%3}, {%4,%5,%6,%7}, {%8,%9}, {%0,%1,%2,%3};"
                 : "+f"(d[0]), "+f"(d[1]), "+f"(d[2]), "+f"(d[3])
                 : "r"(a[0]), "r"(a[1]), "r"(a[2]), "r"(a[3]), "r"(b0), "r"(b1));
}

// ---------------------------------------------------------------------------
// Kernel 1: projection GEMM (tf32 mma.sync)
//   P[b, m0+o, n0+s] = sum_c W[o][c] * X[b][c][s]
// CTA tile 128x128, K=256 in 8 double-buffered k-tiles of 32.
// 8 warps = 2 m-warps x 4 n-warps; warp tile 64x32 (4 m-slabs x 4 n-slabs).
// ---------------------------------------------------------------------------
#define PJ_AS  (128 * 36)     // one A buffer (floats)
#define PJ_BS  (32 * 136)     // one B buffer
#define PJ_SMEM_FLOATS (2 * PJ_AS + 2 * PJ_BS)
#define PJ_SMEM_BYTES  (PJ_SMEM_FLOATS * 4)

__global__ void __launch_bounds__(256) proj_mma(const float* __restrict__ x,
                                                const float* __restrict__ w)
{
    extern __shared__ float sm[];
    float* as = sm;                 // [2][128][36]
    float* bs = sm + 2 * PJ_AS;     // [2][32][136]

    const int b  = blockIdx.z;
    const int m0 = blockIdx.y * 128;
    const int n0 = blockIdx.x * 128;
    const int tid  = threadIdx.x;
    const int wid  = tid >> 5;
    const int lane = tid & 31;
    const int mrow = lane >> 2;     // 0..7
    const int kcol = lane & 3;      // 0..3
    const int wm = wid & 1;         // 2 m-warps
    const int wn = wid >> 1;        // 4 n-warps
    const float* xb = x + b * (Dm * HW);

    float acc[4][4][4] = {};
    float pa[16], pbr[16];

    // prefetch k-tile 0
    #pragma unroll
    for (int q = 0; q < 16; q++) {
        int f = tid + q * 256;
        int o = f >> 5, c = f & 31;
        pa[q]  = w[(m0 + o) * Dm + c];
        int k = f >> 7, n = f & 127;
        pbr[q] = xb[k * HW + n0 + n];
    }
    #pragma unroll
    for (int q = 0; q < 16; q++) {
        int f = tid + q * 256;
        int o = f >> 5, c = f & 31;
        as[o * 36 + c] = f2tf32f(pa[q]);
        int k = f >> 7, n = f & 127;
        bs[k * 136 + n] = f2tf32f(pbr[q]);
    }

    for (int kt = 0; kt < 8; kt++) {
        __syncthreads();
        const int buf = kt & 1;
        // prefetch next k-tile
        if (kt < 7) {
            const int c0 = (kt + 1) * 32;
            #pragma unroll
            for (int q = 0; q < 16; q++) {
                int f = tid + q * 256;
                int o = f >> 5, c = f & 31;
                pa[q]  = w[(m0 + o) * Dm + c0 + c];
                int k = f >> 7, n = f & 127;
                pbr[q] = xb[(c0 + k) * HW + n0 + n];
            }
        }
        // compute current buffer
        const float* ab = as + buf * PJ_AS;
        const float* bb = bs + buf * PJ_BS;
        #pragma unroll
        for (int k8 = 0; k8 < 4; k8++) {
            uint32_t a[4][4];
            #pragma unroll
            for (int msl = 0; msl < 4; msl++) {
                int r0 = wm * 64 + msl * 16 + mrow;
                a[msl][0] = __float_as_uint(ab[r0 * 36 + k8 * 8 + kcol]);
                a[msl][1] = __float_as_uint(ab[(r0 + 8) * 36 + k8 * 8 + kcol]);
                a[msl][2] = __float_as_uint(ab[r0 * 36 + k8 * 8 + 4 + kcol]);
                a[msl][3] = __float_as_uint(ab[(r0 + 8) * 36 + k8 * 8 + 4 + kcol]);
            }
            #pragma unroll
            for (int nsl = 0; nsl < 4; nsl++) {
                int ncol = wn * 32 + nsl * 8 + mrow;
                uint32_t b0 = __float_as_uint(bb[(k8 * 8 + kcol) * 136 + ncol]);
                uint32_t b1 = __float_as_uint(bb[(k8 * 8 + 4 + kcol) * 136 + ncol]);
                #pragma unroll
                for (int msl = 0; msl < 4; msl++)
                    mma16n8k8(acc[msl][nsl], a[msl], b0, b1);
            }
        }
        // store prefetched tile into other buffer
        if (kt < 7) {
            float* an = as + (1 - buf) * PJ_AS;
            float* bn = bs + (1 - buf) * PJ_BS;
            #pragma unroll
            for (int q = 0; q < 16; q++) {
                int f = tid + q * 256;
                int o = f >> 5, c = f & 31;
                an[o * 36 + c] = f2tf32f(pa[q]);
                int k = f >> 7, n = f & 127;
                bn[k * 136 + n] = f2tf32f(pbr[q]);
            }
        }
    }

    float* pb = P_g + b * (OC * HW);
    #pragma unroll
    for (int msl = 0; msl < 4; msl++) {
        #pragma unroll
        for (int nsl = 0; nsl < 4; nsl++) {
            int r0 = m0 + wm * 64 + msl * 16 + mrow;
            int cn = n0 + wn * 32 + nsl * 8 + 2 * kcol;
            *(float2*)&pb[r0 * HW + cn] =
                make_float2(acc[msl][nsl][0], acc[msl][nsl][1]);
            *(float2*)&pb[(r0 + 8) * HW + cn] =
                make_float2(acc[msl][nsl][2], acc[msl][nsl][3]);
        }
    }
}

// ---------------------------------------------------------------------------
// Kernel 2: row attention (unchanged from passing R1 kernel)
// ---------------------------------------------------------------------------
__global__ void row_attn_kernel()
{
    int w  = blockIdx.x;
    int bh = blockIdx.y;
    int b  = bh >> 3, H = bh & 7;
    const float* base = P_g + (b * OC + H * 160) * HW;
    int tid = threadIdx.x;

    __shared__ float q_s[32][64];
    __shared__ float k_s[32][64];
    __shared__ float a_s[64][68];

    for (int f = tid; f < 2048; f += 256) {
        int d = f >> 6, i = f & 63;
        q_s[d][i] = base[(0  + d) * HW + i * 64 + w];
        k_s[d][i] = base[(32 + d) * HW + i * 64 + w];
    }
    __syncthreads();

    int ti = (tid >> 4) * 4;
    int tj = (tid & 15) * 4;
    float acc[4][4] = {};
    #pragma unroll
    for (int d = 0; d < 32; d++) {
        float4 av = *(const float4*)&q_s[d][ti];
        float4 bv = *(const float4*)&k_s[d][tj];
        float avv[4] = {av.x, av.y, av.z, av.w};
        float bvv[4] = {bv.x, bv.y, bv.z, bv.w};
        #pragma unroll
        for (int u = 0; u < 4; u++)
            #pragma unroll
            for (int v2 = 0; v2 < 4; v2++)
                acc[u][v2] += avv[u] * bvv[v2];
    }
    #pragma unroll
    for (int u = 0; u < 4; u++)
        #pragma unroll
        for (int v2 = 0; v2 < 4; v2++)
            a_s[ti + u][tj + v2] = acc[u][v2] * SCALEF;
    __syncthreads();

    if (tid < 64) {
        int j = tid;
        float mx = -1e30f;
        #pragma unroll 8
        for (int i = 0; i < 64; i++) mx = fmaxf(mx, a_s[i][j]);
        float s = 0.f;
        #pragma unroll 8
        for (int i = 0; i < 64; i++) {
            float e = __expf(a_s[i][j] - mx);
            a_s[i][j] = e;
            s += e;
        }
        float inv = 1.f / s;
        float* rb = R_g + bh * (64 * HW);
        #pragma unroll 8
        for (int i = 0; i < 64; i++)
            rb[i * HW + j * 64 + w] = a_s[i][j] * inv;
    }
}

// ---------------------------------------------------------------------------
// Kernel 3: column attention (unchanged)
// ---------------------------------------------------------------------------
__global__ void col_attn_kernel()
{
    int h  = blockIdx.x;
    int bh = blockIdx.y;
    int b  = bh >> 3, H = bh & 7;
    const float* base = P_g + (b * OC + H * 160) * HW;
    int tid = threadIdx.x;

    __shared__ float q_s[32][64];
    __shared__ float k_s[32][64];
    __shared__ float a_s[64][68];

    for (int f = tid; f < 2048; f += 256) {
        int d = f >> 6, i = f & 63;
        q_s[d][i] = base[(64 + d) * HW + h * 64 + i];
        k_s[d][i] = base[(96 + d) * HW + h * 64 + i];
    }
    __syncthreads();

    int ti = (tid >> 4) * 4;
    int tj = (tid & 15) * 4;
    float acc[4][4] = {};
    #pragma unroll
    for (int d = 0; d < 32; d++) {
        float4 av = *(const float4*)&q_s[d][ti];
        float4 bv = *(const float4*)&k_s[d][tj];
        float avv[4] = {av.x, av.y, av.z, av.w};
        float bvv[4] = {bv.x, bv.y, bv.z, bv.w};
        #pragma unroll
        for (int u = 0; u < 4; u++)
            #pragma unroll
            for (int v2 = 0; v2 < 4; v2++)
                acc[u][v2] += avv[u] * bvv[v2];
    }
    #pragma unroll
    for (int u = 0; u < 4; u++)
        #pragma unroll
        for (int v2 = 0; v2 < 4; v2++)
            a_s[ti + u][tj + v2] = acc[u][v2] * SCALEF;
    __syncthreads();

    if (tid < 64) {
        int j = tid;
        float mx = -1e30f;
        #pragma unroll 8
        for (int i = 0; i < 64; i++) mx = fmaxf(mx, a_s[i][j]);
        float s = 0.f;
        #pragma unroll 8
        for (int i = 0; i < 64; i++) {
            float e = __expf(a_s[i][j] - mx);
            a_s[i][j] = e;
            s += e;
        }
        float inv = 1.f / s;
        float* cb = C_g + bh * (64 * HW);
        #pragma unroll 8
        for (int i = 0; i < 64; i++)
            cb[i * HW + h * 64 + j] = a_s[i][j] * inv;
    }
}

// ---------------------------------------------------------------------------
// Kernel 4: fused output via tf32 mma.sync.
//   D[d, hw] = sum_i sum_j V[d, i*64+j] * (r[i,hw]*c[j,hw]);  out = D + v
// mma mapping: m = d (32 = 2 m-slabs), n = hw, k = j (8 per mma).
// CTA: 128 threads (4 warps), covers 256 hw, all 32 d; K-loop over i (64).
// A operand (V panel [32][64]) double-buffered in smem; c tile staged once.
// ---------------------------------------------------------------------------
#define FO_CS  (256 * 68)      // c tile floats
#define FO_VP  (32 * 68)       // one V panel
#define FO_RS  256
#define FO_SMEM_FLOATS (FO_CS + 2 * FO_VP + 2 * FO_RS)
#define FO_SMEM_BYTES  (FO_SMEM_FLOATS * 4)

__global__ void __launch_bounds__(128) fused_out_mma(float* __restrict__ out)
{
    extern __shared__ float sm[];
    float* cs = sm;                       // [256][68]
    float* Vp = sm + FO_CS;               // [2][32][68]
    float* rs = sm + FO_CS + 2 * FO_VP;   // [2][256]

    const int hw0 = blockIdx.x * 256;
    const int bh  = blockIdx.y;
    const int b   = bh >> 3, H = bh & 7;
    const float* vbase = P_g + (b * OC + H * 160 + 128) * HW;
    const float* rbase = R_g + bh * (64 * HW);
    const float* cbase = C_g + bh * (64 * HW);
    const int tid  = threadIdx.x;
    const int wid  = tid >> 5;
    const int lane = tid & 31;
    const int mrow = lane >> 2;   // 0..7
    const int kcol = lane & 3;    // 0..3

    // stage c tile (tf32-rounded): cs[m][j] = c[j][hw0+m]
    for (int f = tid; f < 16384; f += 128) {
        int j = f >> 8, m = f & 255;
        cs[m * 68 + j] = f2tf32f(cbase[j * HW + hw0 + m]);
    }
    // stage V panel + r row for i = 0 into buffer 0
    {
        #pragma unroll
        for (int q = 0; q < 16; q++) {
            int f = tid + q * 128;
            int d = f >> 6, j = f & 63;
            Vp[d * 68 + j] = f2tf32f(vbase[d * HW + j]);
        }
        rs[tid]       = rbase[hw0 + tid];
        rs[tid + 128] = rbase[hw0 + tid + 128];
    }

    float acc[2][8][4] = {};
    float pv[16], pr0, pr1;

    for (int i = 0; i < 64; i++) {
        __syncthreads();
        const int cur = i & 1;
        // prefetch i+1
        if (i < 63) {
            const float* vsrc = vbase + (i + 1) * 64;
            #pragma unroll
            for (int q = 0; q < 16; q++) {
                int f = tid + q * 128;
                int d = f >> 6, j = f & 63;
                pv[q] = vsrc[d * HW + j];
            }
            pr0 = rbase[(i + 1) * HW + hw0 + tid];
            pr1 = rbase[(i + 1) * HW + hw0 + tid + 128];
        }
        // compute on buffer cur
        const float* vp = Vp + cur * FO_VP;
        const float* rr = rs + cur * FO_RS;
        float rv[8];
        #pragma unroll
        for (int ns = 0; ns < 8; ns++)
            rv[ns] = rr[wid * 64 + ns * 8 + mrow];

        #pragma unroll
        for (int jc = 0; jc < 8; jc++) {
            uint32_t a[2][4];
            #pragma unroll
            for (int ms = 0; ms < 2; ms++) {
                int d0 = ms * 16 + mrow;
                a[ms][0] = __float_as_uint(vp[d0 * 68 + jc * 8 + kcol]);
                a[ms][1] = __float_as_uint(vp[(d0 + 8) * 68 + jc * 8 + kcol]);
                a[ms][2] = __float_as_uint(vp[d0 * 68 + jc * 8 + 4 + kcol]);
                a[ms][3] = __float_as_uint(vp[(d0 + 8) * 68 + jc * 8 + 4 + kcol]);
            }
            #pragma unroll
            for (int ns = 0; ns < 8; ns++) {
                int hwl = wid * 64 + ns * 8 + mrow;
                float c0 = cs[hwl * 68 + jc * 8 + kcol];
                float c1 = cs[hwl * 68 + jc * 8 + 4 + kcol];
                uint32_t b0 = f2tf32(rv[ns] * c0);
                uint32_t b1 = f2tf32(rv[ns] * c1);
                mma16n8k8(acc[0][ns], a[0], b0, b1);
                mma16n8k8(acc[1][ns], a[1], b0, b1);
            }
        }
        // store prefetched panel into other buffer
        if (i < 63) {
            float* vn = Vp + (1 - cur) * FO_VP;
            float* rn = rs + (1 - cur) * FO_RS;
            #pragma unroll
            for (int q = 0; q < 16; q++) {
                int f = tid + q * 128;
                int d = f >> 6, j = f & 63;
                vn[d * 68 + j] = f2tf32f(pv[q]);
            }
            rn[tid]       = pr0;
            rn[tid + 128] = pr1;
        }
    }

    // epilogue: out[d][hw] = acc + v
    float* ob = out + (b * 256 + H * 32) * HW;
    #pragma unroll
    for (int ms = 0; ms < 2; ms++) {
        #pragma unroll
        for (int ns = 0; ns < 8; ns++) {
            int d0  = ms * 16 + mrow;
            int col = hw0 + wid * 64 + ns * 8 + 2 * kcol;
            float2 v0 = *(const float2*)&vbase[d0 * HW + col];
            float2 v1 = *(const float2*)&vbase[(d0 + 8) * HW + col];
            *(float2*)&ob[d0 * HW + col] =
                make_float2(acc[ms][ns][0] + v0.x, acc[ms][ns][1] + v0.y);
            *(float2*)&ob[(d0 + 8) * HW + col] =
                make_float2(acc[ms][ns][2] + v1.x, acc[ms][ns][3] + v1.y);
        }
    }
}

// ---------------------------------------------------------------------------
extern "C" void kernel_launch(void* const* d_in, const int* in_sizes, int n_in,
                              void* d_out, int out_size)
{
    const float* x = (const float*)d_in[0];
    const float* w = (const float*)d_in[1];
    if (n_in >= 2 && in_sizes[0] == 327680 && in_sizes[1] == 2097152) {
        const float* t = x; x = w; w = t;
    }
    float* out = (float*)d_out;

    static int attr_set = 0;
    if (!attr_set) {
        cudaFuncSetAttribute(proj_mma, cudaFuncAttributeMaxDynamicSharedMemorySize,
                             PJ_SMEM_BYTES);
        cudaFuncSetAttribute(fused_out_mma, cudaFuncAttributeMaxDynamicSharedMemorySize,
                             FO_SMEM_BYTES);
        attr_set = 1;
    }

    dim3 g1(32, 10, 2);
    proj_mma<<<g1, 256, PJ_SMEM_BYTES>>>(x, w);

    dim3 g2(64, 16);
    row_attn_kernel<<<g2, 256>>>();
    col_attn_kernel<<<g2, 256>>>();

    dim3 g4(16, 16);
    fused_out_mma<<<g4, 128, FO_SMEM_BYTES>>>(out);
}

// round 6
// speedup vs baseline: 2.9652x; 1.1636x over previous
#include <cuda_runtime.h>
#include <cstdint>

#define NHh 8
#define Dm 256          // NH*HD
#define OC 1280         // NH*(4*KD+HD)
#define HW 4096
#define NB 2
#define SCALEF 0.17677669529663687f

// Scratch (device globals; no runtime allocation allowed)
__device__ float P_g[NB * OC * HW];            // [b][o][hw]
__device__ float R_g[NB * NHh * 64 * HW];      // [b][H][i][hw] row softmax
__device__ float C_g[NB * NHh * 64 * HW];      // [b][H][j][hw] col softmax

// ---------------------------------------------------------------------------
// helpers: tf32 rounding + mma.sync (sm_80+ PTX, works on plain sm_103 target)
// ---------------------------------------------------------------------------
__device__ __forceinline__ uint32_t f2tf32(float x) {
    uint32_t u;
    asm("cvt.rna.tf32.f32 %0, %1;" : "=r"(u) : "f"(x));
    return u;
}
__device__ __forceinline__ float f2tf32f(float x) {
    uint32_t u = f2tf32(x);
    return __uint_as_float(u);
}
__device__ __forceinline__ void mma16n8k8(float* d, const uint32_t* a,
                                          uint32_t b0, uint32_t b1) {
    asm volatile("mma.sync.aligned.m16n8k8.row.col.f32.tf32.tf32.f32 "
                 "{%0,%1,%2,%3}, {%4,%5,%6,%7}, {%8,%9}, {%0,%1,%2,%3};"
                 : "+f"(d[0]), "+f"(d[1]), "+f"(d[2]), "+f"(d[3])
                 : "r"(a[0]), "r"(a[1]), "r"(a[2]), "r"(a[3]), "r"(b0), "r"(b1));
}

// ---------------------------------------------------------------------------
// Kernel 1: projection GEMM (tf32 mma.sync)  -- now launch_bounds(256,2)
// ---------------------------------------------------------------------------
#define PJ_AS  (128 * 36)
#define PJ_BS  (32 * 136)
#define PJ_SMEM_FLOATS (2 * PJ_AS + 2 * PJ_BS)
#define PJ_SMEM_BYTES  (PJ_SMEM_FLOATS * 4)

__global__ void __launch_bounds__(256, 2) proj_mma(const float* __restrict__ x,
                                                   const float* __restrict__ w)
{
    extern __shared__ float sm[];
    float* as = sm;                 // [2][128][36]
    float* bs = sm + 2 * PJ_AS;     // [2][32][136]

    const int b  = blockIdx.z;
    const int m0 = blockIdx.y * 128;
    const int n0 = blockIdx.x * 128;
    const int tid  = threadIdx.x;
    const int wid  = tid >> 5;
    const int lane = tid & 31;
    const int mrow = lane >> 2;
    const int kcol = lane & 3;
    const int wm = wid & 1;
    const int wn = wid >> 1;
    const float* xb = x + b * (Dm * HW);

    float acc[4][4][4] = {};
    float pa[16], pbr[16];

    #pragma unroll
    for (int q = 0; q < 16; q++) {
        int f = tid + q * 256;
        int o = f >> 5, c = f & 31;
        pa[q]  = w[(m0 + o) * Dm + c];
        int k = f >> 7, n = f & 127;
        pbr[q] = xb[k * HW + n0 + n];
    }
    #pragma unroll
    for (int q = 0; q < 16; q++) {
        int f = tid + q * 256;
        int o = f >> 5, c = f & 31;
        as[o * 36 + c] = f2tf32f(pa[q]);
        int k = f >> 7, n = f & 127;
        bs[k * 136 + n] = f2tf32f(pbr[q]);
    }

    for (int kt = 0; kt < 8; kt++) {
        __syncthreads();
        const int buf = kt & 1;
        if (kt < 7) {
            const int c0 = (kt + 1) * 32;
            #pragma unroll
            for (int q = 0; q < 16; q++) {
                int f = tid + q * 256;
                int o = f >> 5, c = f & 31;
                pa[q]  = w[(m0 + o) * Dm + c0 + c];
                int k = f >> 7, n = f & 127;
                pbr[q] = xb[(c0 + k) * HW + n0 + n];
            }
        }
        const float* ab = as + buf * PJ_AS;
        const float* bb = bs + buf * PJ_BS;
        #pragma unroll
        for (int k8 = 0; k8 < 4; k8++) {
            uint32_t a[4][4];
            #pragma unroll
            for (int msl = 0; msl < 4; msl++) {
                int r0 = wm * 64 + msl * 16 + mrow;
                a[msl][0] = __float_as_uint(ab[r0 * 36 + k8 * 8 + kcol]);
                a[msl][1] = __float_as_uint(ab[(r0 + 8) * 36 + k8 * 8 + kcol]);
                a[msl][2] = __float_as_uint(ab[r0 * 36 + k8 * 8 + 4 + kcol]);
                a[msl][3] = __float_as_uint(ab[(r0 + 8) * 36 + k8 * 8 + 4 + kcol]);
            }
            #pragma unroll
            for (int nsl = 0; nsl < 4; nsl++) {
                int ncol = wn * 32 + nsl * 8 + mrow;
                uint32_t b0 = __float_as_uint(bb[(k8 * 8 + kcol) * 136 + ncol]);
                uint32_t b1 = __float_as_uint(bb[(k8 * 8 + 4 + kcol) * 136 + ncol]);
                #pragma unroll
                for (int msl = 0; msl < 4; msl++)
                    mma16n8k8(acc[msl][nsl], a[msl], b0, b1);
            }
        }
        if (kt < 7) {
            float* an = as + (1 - buf) * PJ_AS;
            float* bn = bs + (1 - buf) * PJ_BS;
            #pragma unroll
            for (int q = 0; q < 16; q++) {
                int f = tid + q * 256;
                int o = f >> 5, c = f & 31;
                an[o * 36 + c] = f2tf32f(pa[q]);
                int k = f >> 7, n = f & 127;
                bn[k * 136 + n] = f2tf32f(pbr[q]);
            }
        }
    }

    float* pb = P_g + b * (OC * HW);
    #pragma unroll
    for (int msl = 0; msl < 4; msl++) {
        #pragma unroll
        for (int nsl = 0; nsl < 4; nsl++) {
            int r0 = m0 + wm * 64 + msl * 16 + mrow;
            int cn = n0 + wn * 32 + nsl * 8 + 2 * kcol;
            *(float2*)&pb[r0 * HW + cn] =
                make_float2(acc[msl][nsl][0], acc[msl][nsl][1]);
            *(float2*)&pb[(r0 + 8) * HW + cn] =
                make_float2(acc[msl][nsl][2], acc[msl][nsl][3]);
        }
    }
}

// ---------------------------------------------------------------------------
// Kernel 2: row attention, w-quad version (coalescing fix).
// CTA = (b,H, 4 consecutive w).  grid (16, 16), 256 threads.
// Phase 1: load q/k for 4 w (8-sector requests).  Phase 2: scores in regs
// (each 64-thread group owns one w; 8x8 tile per thread).  Phase 3: scores
// -> smem (reusing q/k storage).  Phase 4: softmax over i, all 256 threads
// (thread = (j, ww)), stores in 4-consecutive chunks.
// ---------------------------------------------------------------------------
#define QSTR (32 * 65 + 1)              // per-w q/k pitch (floats)
#define ASTR (64 * 65 + 1)              // per-w score pitch
#define RA_SMEM_FLOATS (8 * QSTR)       // 16648 >= 4*ASTR (16644)
#define RA_SMEM_BYTES  (RA_SMEM_FLOATS * 4)

__global__ void __launch_bounds__(256) row_attn4()
{
    extern __shared__ float smb[];
    float* q_s = smb;                   // [4][QSTR]: [ww][d*65+i]
    float* k_s = smb + 4 * QSTR;

    const int w0 = blockIdx.x * 4;
    const int bh = blockIdx.y;
    const int b  = bh >> 3, H = bh & 7;
    const float* qb = P_g + (b * OC + H * 160) * HW;
    const float* kb = qb + 32 * HW;
    const int tid = threadIdx.x;

    for (int e = tid; e < 8192; e += 256) {
        int ww = e & 3, i = (e >> 2) & 63, d = e >> 8;
        q_s[ww * QSTR + d * 65 + i] = qb[d * HW + i * 64 + w0 + ww];
        k_s[ww * QSTR + d * 65 + i] = kb[d * HW + i * 64 + w0 + ww];
    }
    __syncthreads();

    // scores in registers: 64-thread group per ww, 8x8 tile each
    const int ww = tid >> 6;
    const int gt = tid & 63;
    const int ti = (gt >> 3) * 8;
    const int tj = (gt & 7) * 8;
    const float* qq = q_s + ww * QSTR;
    const float* kk = k_s + ww * QSTR;

    float acc[8][8] = {};
    #pragma unroll 4
    for (int d = 0; d < 32; d++) {
        float qv[8], kv[8];
        #pragma unroll
        for (int u = 0; u < 8; u++) qv[u] = qq[d * 65 + ti + u];
        #pragma unroll
        for (int v = 0; v < 8; v++) kv[v] = kk[d * 65 + tj + v];
        #pragma unroll
        for (int u = 0; u < 8; u++)
            #pragma unroll
            for (int v = 0; v < 8; v++)
                acc[u][v] += qv[u] * kv[v];
    }
    __syncthreads();   // q/k fully consumed; reuse smem for scores

    float* a_s = smb;                   // [4][ASTR]: [ww][i*65+j]
    #pragma unroll
    for (int u = 0; u < 8; u++)
        #pragma unroll
        for (int v = 0; v < 8; v++)
            a_s[ww * ASTR + (ti + u) * 65 + (tj + v)] = acc[u][v] * SCALEF;
    __syncthreads();

    // softmax over i; thread owns column (j, ww2)
    {
        const int ww2 = tid & 3;
        const int j   = tid >> 2;
        float* col = a_s + ww2 * ASTR + j;
        float mx = -1e30f;
        #pragma unroll 8
        for (int i = 0; i < 64; i++) mx = fmaxf(mx, col[i * 65]);
        float s = 0.f;
        #pragma unroll 8
        for (int i = 0; i < 64; i++) {
            float e = __expf(col[i * 65] - mx);
            col[i * 65] = e;
            s += e;
        }
        float inv = 1.f / s;
        float* rb = R_g + bh * (64 * HW) + j * 64 + w0 + ww2;
        #pragma unroll 8
        for (int i = 0; i < 64; i++)
            rb[i * HW] = col[i * 65] * inv;
    }
}

// ---------------------------------------------------------------------------
// Kernel 3: column attention (unchanged; already coalesced)
// ---------------------------------------------------------------------------
__global__ void col_attn_kernel()
{
    int h  = blockIdx.x;
    int bh = blockIdx.y;
    int b  = bh >> 3, H = bh & 7;
    const float* base = P_g + (b * OC + H * 160) * HW;
    int tid = threadIdx.x;

    __shared__ float q_s[32][64];
    __shared__ float k_s[32][64];
    __shared__ float a_s[64][68];

    for (int f = tid; f < 2048; f += 256) {
        int d = f >> 6, i = f & 63;
        q_s[d][i] = base[(64 + d) * HW + h * 64 + i];
        k_s[d][i] = base[(96 + d) * HW + h * 64 + i];
    }
    __syncthreads();

    int ti = (tid >> 4) * 4;
    int tj = (tid & 15) * 4;
    float acc[4][4] = {};
    #pragma unroll
    for (int d = 0; d < 32; d++) {
        float4 av = *(const float4*)&q_s[d][ti];
        float4 bv = *(const float4*)&k_s[d][tj];
        float avv[4] = {av.x, av.y, av.z, av.w};
        float bvv[4] = {bv.x, bv.y, bv.z, bv.w};
        #pragma unroll
        for (int u = 0; u < 4; u++)
            #pragma unroll
            for (int v2 = 0; v2 < 4; v2++)
                acc[u][v2] += avv[u] * bvv[v2];
    }
    #pragma unroll
    for (int u = 0; u < 4; u++)
        #pragma unroll
        for (int v2 = 0; v2 < 4; v2++)
            a_s[ti + u][tj + v2] = acc[u][v2] * SCALEF;
    __syncthreads();

    if (tid < 64) {
        int j = tid;
        float mx = -1e30f;
        #pragma unroll 8
        for (int i = 0; i < 64; i++) mx = fmaxf(mx, a_s[i][j]);
        float s = 0.f;
        #pragma unroll 8
        for (int i = 0; i < 64; i++) {
            float e = __expf(a_s[i][j] - mx);
            a_s[i][j] = e;
            s += e;
        }
        float inv = 1.f / s;
        float* cb = C_g + bh * (64 * HW);
        #pragma unroll 8
        for (int i = 0; i < 64; i++)
            cb[i * HW + h * 64 + j] = a_s[i][j] * inv;
    }
}

// ---------------------------------------------------------------------------
// Kernel 4: fused output via tf32 mma.sync — occupancy version.
// CTA: 128 threads (4 warps), hw tile 128 (warp = 32 hw), smem 53KB -> 4 CTA/SM.
//   D[d, hw] = sum_i sum_j V[d, i*64+j] * (r[i,hw]*c[j,hw]);  out = D + v
// ---------------------------------------------------------------------------
#define FO_CS  (128 * 68)      // c tile floats
#define FO_VP  (32 * 68)       // one V panel
#define FO_RS  128
#define FO_SMEM_FLOATS (FO_CS + 2 * FO_VP + 2 * FO_RS)
#define FO_SMEM_BYTES  (FO_SMEM_FLOATS * 4)

__global__ void __launch_bounds__(128, 4) fused_out_mma(float* __restrict__ out)
{
    extern __shared__ float sm[];
    float* cs = sm;                       // [128][68]
    float* Vp = sm + FO_CS;               // [2][32][68]
    float* rs = sm + FO_CS + 2 * FO_VP;   // [2][128]

    const int hw0 = blockIdx.x * 128;
    const int bh  = blockIdx.y;
    const int b   = bh >> 3, H = bh & 7;
    const float* vbase = P_g + (b * OC + H * 160 + 128) * HW;
    const float* rbase = R_g + bh * (64 * HW);
    const float* cbase = C_g + bh * (64 * HW);
    const int tid  = threadIdx.x;
    const int wid  = tid >> 5;
    const int lane = tid & 31;
    const int mrow = lane >> 2;   // 0..7
    const int kcol = lane & 3;    // 0..3

    // stage c tile (tf32-rounded): cs[m][j] = c[j][hw0+m]
    for (int f = tid; f < 8192; f += 128) {
        int j = f >> 7, m = f & 127;
        cs[m * 68 + j] = f2tf32f(cbase[j * HW + hw0 + m]);
    }
    // stage V panel + r row for i = 0 into buffer 0
    {
        #pragma unroll
        for (int q = 0; q < 16; q++) {
            int f = tid + q * 128;
            int d = f >> 6, j = f & 63;
            Vp[d * 68 + j] = f2tf32f(vbase[d * HW + j]);
        }
        rs[tid] = rbase[hw0 + tid];
    }

    float acc[2][4][4] = {};
    float pv[16], pr;

    for (int i = 0; i < 64; i++) {
        __syncthreads();
        const int cur = i & 1;
        if (i < 63) {
            const float* vsrc = vbase + (i + 1) * 64;
            #pragma unroll
            for (int q = 0; q < 16; q++) {
                int f = tid + q * 128;
                int d = f >> 6, j = f & 63;
                pv[q] = vsrc[d * HW + j];
            }
            pr = rbase[(i + 1) * HW + hw0 + tid];
        }
        const float* vp = Vp + cur * FO_VP;
        const float* rr = rs + cur * FO_RS;
        float rv[4];
        #pragma unroll
        for (int ns = 0; ns < 4; ns++)
            rv[ns] = rr[wid * 32 + ns * 8 + mrow];

        #pragma unroll
        for (int jc = 0; jc < 8; jc++) {
            uint32_t a[2][4];
            #pragma unroll
            for (int ms = 0; ms < 2; ms++) {
                int d0 = ms * 16 + mrow;
                a[ms][0] = __float_as_uint(vp[d0 * 68 + jc * 8 + kcol]);
                a[ms][1] = __float_as_uint(vp[(d0 + 8) * 68 + jc * 8 + kcol]);
                a[ms][2] = __float_as_uint(vp[d0 * 68 + jc * 8 + 4 + kcol]);
                a[ms][3] = __float_as_uint(vp[(d0 + 8) * 68 + jc * 8 + 4 + kcol]);
            }
            #pragma unroll
            for (int ns = 0; ns < 4; ns++) {
                int hwl = wid * 32 + ns * 8 + mrow;
                float c0 = cs[hwl * 68 + jc * 8 + kcol];
                float c1 = cs[hwl * 68 + jc * 8 + 4 + kcol];
                uint32_t b0 = f2tf32(rv[ns] * c0);
                uint32_t b1 = f2tf32(rv[ns] * c1);
                mma16n8k8(acc[0][ns], a[0], b0, b1);
                mma16n8k8(acc[1][ns], a[1], b0, b1);
            }
        }
        if (i < 63) {
            float* vn = Vp + (1 - cur) * FO_VP;
            float* rn = rs + (1 - cur) * FO_RS;
            #pragma unroll
            for (int q = 0; q < 16; q++) {
                int f = tid + q * 128;
                int d = f >> 6, j = f & 63;
                vn[d * 68 + j] = f2tf32f(pv[q]);
            }
            rn[tid] = pr;
        }
    }

    // epilogue: out[d][hw] = acc + v
    float* ob = out + (b * 256 + H * 32) * HW;
    #pragma unroll
    for (int ms = 0; ms < 2; ms++) {
        #pragma unroll
        for (int ns = 0; ns < 4; ns++) {
            int d0  = ms * 16 + mrow;
            int col = hw0 + wid * 32 + ns * 8 + 2 * kcol;
            float2 v0 = *(const float2*)&vbase[d0 * HW + col];
            float2 v1 = *(const float2*)&vbase[(d0 + 8) * HW + col];
            *(float2*)&ob[d0 * HW + col] =
                make_float2(acc[ms][ns][0] + v0.x, acc[ms][ns][1] + v0.y);
            *(float2*)&ob[(d0 + 8) * HW + col] =
                make_float2(acc[ms][ns][2] + v1.x, acc[ms][ns][3] + v1.y);
        }
    }
}

// ---------------------------------------------------------------------------
extern "C" void kernel_launch(void* const* d_in, const int* in_sizes, int n_in,
                              void* d_out, int out_size)
{
    const float* x = (const float*)d_in[0];
    const float* w = (const float*)d_in[1];
    if (n_in >= 2 && in_sizes[0] == 327680 && in_sizes[1] == 2097152) {
        const float* t = x; x = w; w = t;
    }
    float* out = (float*)d_out;

    static int attr_set = 0;
    if (!attr_set) {
        cudaFuncSetAttribute(proj_mma, cudaFuncAttributeMaxDynamicSharedMemorySize,
                             PJ_SMEM_BYTES);
        cudaFuncSetAttribute(row_attn4, cudaFuncAttributeMaxDynamicSharedMemorySize,
                             RA_SMEM_BYTES);
        cudaFuncSetAttribute(fused_out_mma, cudaFuncAttributeMaxDynamicSharedMemorySize,
                             FO_SMEM_BYTES);
        attr_set = 1;
    }

    dim3 g1(32, 10, 2);
    proj_mma<<<g1, 256, PJ_SMEM_BYTES>>>(x, w);

    dim3 g2r(16, 16);
    row_attn4<<<g2r, 256, RA_SMEM_BYTES>>>();
    dim3 g2c(64, 16);
    col_attn_kernel<<<g2c, 256>>>();

    dim3 g4(32, 16);
    fused_out_mma<<<g4, 128, FO_SMEM_BYTES>>>(out);
}

// round 7
// speedup vs baseline: 3.0580x; 1.0313x over previous
#include <cuda_runtime.h>
#include <cstdint>

#define NHh 8
#define Dm 256          // NH*HD
#define OC 1280         // NH*(4*KD+HD)
#define HW 4096
#define NB 2
#define SCALEF 0.17677669529663687f

// Scratch (device globals; no runtime allocation allowed)
__device__ float P_g[NB * OC * HW];            // [b][o][hw]
__device__ float R_g[NB * NHh * 64 * HW];      // [b][H][i][hw] row softmax
__device__ float C_g[NB * NHh * 64 * HW];      // [b][H][j][hw] col softmax

// ---------------------------------------------------------------------------
// helpers: tf32 rounding + mma.sync (sm_80+ PTX, works on plain sm_103 target)
// ---------------------------------------------------------------------------
__device__ __forceinline__ uint32_t f2tf32(float x) {
    uint32_t u;
    asm("cvt.rna.tf32.f32 %0, %1;" : "=r"(u) : "f"(x));
    return u;
}
__device__ __forceinline__ float f2tf32f(float x) {
    uint32_t u = f2tf32(x);
    return __uint_as_float(u);
}
__device__ __forceinline__ void mma16n8k8(float* d, const uint32_t* a,
                                          uint32_t b0, uint32_t b1) {
    asm volatile("mma.sync.aligned.m16n8k8.row.col.f32.tf32.tf32.f32 "
                 "{%0,%1,%2,%3}, {%4,%5,%6,%7}, {%8,%9}, {%0,%1,%2,%3};"
                 : "+f"(d[0]), "+f"(d[1]), "+f"(d[2]), "+f"(d[3])
                 : "r"(a[0]), "r"(a[1]), "r"(a[2]), "r"(a[3]), "r"(b0), "r"(b1));
}
// zero-C variant: D = A*B (fresh accumulator, no MOV-zero needed)
__device__ __forceinline__ void mma16n8k8_z(float* d, const uint32_t* a,
                                            uint32_t b0, uint32_t b1) {
    asm volatile("mma.sync.aligned.m16n8k8.row.col.f32.tf32.tf32.f32 "
                 "{%0,%1,%2,%3}, {%4,%5,%6,%7}, {%8,%9}, {%10,%10,%10,%10};"
                 : "=f"(d[0]), "=f"(d[1]), "=f"(d[2]), "=f"(d[3])
                 : "r"(a[0]), "r"(a[1]), "r"(a[2]), "r"(a[3]), "r"(b0), "r"(b1),
                   "f"(0.0f));
}

// ---------------------------------------------------------------------------
// Kernel 1: projection GEMM (tf32 mma.sync)  (unchanged)
// ---------------------------------------------------------------------------
#define PJ_AS  (128 * 36)
#define PJ_BS  (32 * 136)
#define PJ_SMEM_FLOATS (2 * PJ_AS + 2 * PJ_BS)
#define PJ_SMEM_BYTES  (PJ_SMEM_FLOATS * 4)

__global__ void __launch_bounds__(256, 2) proj_mma(const float* __restrict__ x,
                                                   const float* __restrict__ w)
{
    extern __shared__ float sm[];
    float* as = sm;                 // [2][128][36]
    float* bs = sm + 2 * PJ_AS;     // [2][32][136]

    const int b  = blockIdx.z;
    const int m0 = blockIdx.y * 128;
    const int n0 = blockIdx.x * 128;
    const int tid  = threadIdx.x;
    const int wid  = tid >> 5;
    const int lane = tid & 31;
    const int mrow = lane >> 2;
    const int kcol = lane & 3;
    const int wm = wid & 1;
    const int wn = wid >> 1;
    const float* xb = x + b * (Dm * HW);

    float acc[4][4][4] = {};
    float pa[16], pbr[16];

    #pragma unroll
    for (int q = 0; q < 16; q++) {
        int f = tid + q * 256;
        int o = f >> 5, c = f & 31;
        pa[q]  = w[(m0 + o) * Dm + c];
        int k = f >> 7, n = f & 127;
        pbr[q] = xb[k * HW + n0 + n];
    }
    #pragma unroll
    for (int q = 0; q < 16; q++) {
        int f = tid + q * 256;
        int o = f >> 5, c = f & 31;
        as[o * 36 + c] = f2tf32f(pa[q]);
        int k = f >> 7, n = f & 127;
        bs[k * 136 + n] = f2tf32f(pbr[q]);
    }

    for (int kt = 0; kt < 8; kt++) {
        __syncthreads();
        const int buf = kt & 1;
        if (kt < 7) {
            const int c0 = (kt + 1) * 32;
            #pragma unroll
            for (int q = 0; q < 16; q++) {
                int f = tid + q * 256;
                int o = f >> 5, c = f & 31;
                pa[q]  = w[(m0 + o) * Dm + c0 + c];
                int k = f >> 7, n = f & 127;
                pbr[q] = xb[(c0 + k) * HW + n0 + n];
            }
        }
        const float* ab = as + buf * PJ_AS;
        const float* bb = bs + buf * PJ_BS;
        #pragma unroll
        for (int k8 = 0; k8 < 4; k8++) {
            uint32_t a[4][4];
            #pragma unroll
            for (int msl = 0; msl < 4; msl++) {
                int r0 = wm * 64 + msl * 16 + mrow;
                a[msl][0] = __float_as_uint(ab[r0 * 36 + k8 * 8 + kcol]);
                a[msl][1] = __float_as_uint(ab[(r0 + 8) * 36 + k8 * 8 + kcol]);
                a[msl][2] = __float_as_uint(ab[r0 * 36 + k8 * 8 + 4 + kcol]);
                a[msl][3] = __float_as_uint(ab[(r0 + 8) * 36 + k8 * 8 + 4 + kcol]);
            }
            #pragma unroll
            for (int nsl = 0; nsl < 4; nsl++) {
                int ncol = wn * 32 + nsl * 8 + mrow;
                uint32_t b0 = __float_as_uint(bb[(k8 * 8 + kcol) * 136 + ncol]);
                uint32_t b1 = __float_as_uint(bb[(k8 * 8 + 4 + kcol) * 136 + ncol]);
                #pragma unroll
                for (int msl = 0; msl < 4; msl++)
                    mma16n8k8(acc[msl][nsl], a[msl], b0, b1);
            }
        }
        if (kt < 7) {
            float* an = as + (1 - buf) * PJ_AS;
            float* bn = bs + (1 - buf) * PJ_BS;
            #pragma unroll
            for (int q = 0; q < 16; q++) {
                int f = tid + q * 256;
                int o = f >> 5, c = f & 31;
                an[o * 36 + c] = f2tf32f(pa[q]);
                int k = f >> 7, n = f & 127;
                bn[k * 136 + n] = f2tf32f(pbr[q]);
            }
        }
    }

    float* pb = P_g + b * (OC * HW);
    #pragma unroll
    for (int msl = 0; msl < 4; msl++) {
        #pragma unroll
        for (int nsl = 0; nsl < 4; nsl++) {
            int r0 = m0 + wm * 64 + msl * 16 + mrow;
            int cn = n0 + wn * 32 + nsl * 8 + 2 * kcol;
            *(float2*)&pb[r0 * HW + cn] =
                make_float2(acc[msl][nsl][0], acc[msl][nsl][1]);
            *(float2*)&pb[(r0 + 8) * HW + cn] =
                make_float2(acc[msl][nsl][2], acc[msl][nsl][3]);
        }
    }
}

// ---------------------------------------------------------------------------
// Kernel 2: row attention, w-quad version (unchanged)
// ---------------------------------------------------------------------------
#define QSTR (32 * 65 + 1)
#define ASTR (64 * 65 + 1)
#define RA_SMEM_FLOATS (8 * QSTR)
#define RA_SMEM_BYTES  (RA_SMEM_FLOATS * 4)

__global__ void __launch_bounds__(256) row_attn4()
{
    extern __shared__ float smb[];
    float* q_s = smb;
    float* k_s = smb + 4 * QSTR;

    const int w0 = blockIdx.x * 4;
    const int bh = blockIdx.y;
    const int b  = bh >> 3, H = bh & 7;
    const float* qb = P_g + (b * OC + H * 160) * HW;
    const float* kb = qb + 32 * HW;
    const int tid = threadIdx.x;

    for (int e = tid; e < 8192; e += 256) {
        int ww = e & 3, i = (e >> 2) & 63, d = e >> 8;
        q_s[ww * QSTR + d * 65 + i] = qb[d * HW + i * 64 + w0 + ww];
        k_s[ww * QSTR + d * 65 + i] = kb[d * HW + i * 64 + w0 + ww];
    }
    __syncthreads();

    const int ww = tid >> 6;
    const int gt = tid & 63;
    const int ti = (gt >> 3) * 8;
    const int tj = (gt & 7) * 8;
    const float* qq = q_s + ww * QSTR;
    const float* kk = k_s + ww * QSTR;

    float acc[8][8] = {};
    #pragma unroll 4
    for (int d = 0; d < 32; d++) {
        float qv[8], kv[8];
        #pragma unroll
        for (int u = 0; u < 8; u++) qv[u] = qq[d * 65 + ti + u];
        #pragma unroll
        for (int v = 0; v < 8; v++) kv[v] = kk[d * 65 + tj + v];
        #pragma unroll
        for (int u = 0; u < 8; u++)
            #pragma unroll
            for (int v = 0; v < 8; v++)
                acc[u][v] += qv[u] * kv[v];
    }
    __syncthreads();

    float* a_s = smb;
    #pragma unroll
    for (int u = 0; u < 8; u++)
        #pragma unroll
        for (int v = 0; v < 8; v++)
            a_s[ww * ASTR + (ti + u) * 65 + (tj + v)] = acc[u][v] * SCALEF;
    __syncthreads();

    {
        const int ww2 = tid & 3;
        const int j   = tid >> 2;
        float* col = a_s + ww2 * ASTR + j;
        float mx = -1e30f;
        #pragma unroll 8
        for (int i = 0; i < 64; i++) mx = fmaxf(mx, col[i * 65]);
        float s = 0.f;
        #pragma unroll 8
        for (int i = 0; i < 64; i++) {
            float e = __expf(col[i * 65] - mx);
            col[i * 65] = e;
            s += e;
        }
        float inv = 1.f / s;
        float* rb = R_g + bh * (64 * HW) + j * 64 + w0 + ww2;
        #pragma unroll 8
        for (int i = 0; i < 64; i++)
            rb[i * HW] = col[i * 65] * inv;
    }
}

// ---------------------------------------------------------------------------
// Kernel 3: column attention (unchanged)
// ---------------------------------------------------------------------------
__global__ void col_attn_kernel()
{
    int h  = blockIdx.x;
    int bh = blockIdx.y;
    int b  = bh >> 3, H = bh & 7;
    const float* base = P_g + (b * OC + H * 160) * HW;
    int tid = threadIdx.x;

    __shared__ float q_s[32][64];
    __shared__ float k_s[32][64];
    __shared__ float a_s[64][68];

    for (int f = tid; f < 2048; f += 256) {
        int d = f >> 6, i = f & 63;
        q_s[d][i] = base[(64 + d) * HW + h * 64 + i];
        k_s[d][i] = base[(96 + d) * HW + h * 64 + i];
    }
    __syncthreads();

    int ti = (tid >> 4) * 4;
    int tj = (tid & 15) * 4;
    float acc[4][4] = {};
    #pragma unroll
    for (int d = 0; d < 32; d++) {
        float4 av = *(const float4*)&q_s[d][ti];
        float4 bv = *(const float4*)&k_s[d][tj];
        float avv[4] = {av.x, av.y, av.z, av.w};
        float bvv[4] = {bv.x, bv.y, bv.z, bv.w};
        #pragma unroll
        for (int u = 0; u < 4; u++)
            #pragma unroll
            for (int v2 = 0; v2 < 4; v2++)
                acc[u][v2] += avv[u] * bvv[v2];
    }
    #pragma unroll
    for (int u = 0; u < 4; u++)
        #pragma unroll
        for (int v2 = 0; v2 < 4; v2++)
            a_s[ti + u][tj + v2] = acc[u][v2] * SCALEF;
    __syncthreads();

    if (tid < 64) {
        int j = tid;
        float mx = -1e30f;
        #pragma unroll 8
        for (int i = 0; i < 64; i++) mx = fmaxf(mx, a_s[i][j]);
        float s = 0.f;
        #pragma unroll 8
        for (int i = 0; i < 64; i++) {
            float e = __expf(a_s[i][j] - mx);
            a_s[i][j] = e;
            s += e;
        }
        float inv = 1.f / s;
        float* cb = C_g + bh * (64 * HW);
        #pragma unroll 8
        for (int i = 0; i < 64; i++)
            cb[i * HW + h * 64 + j] = a_s[i][j] * inv;
    }
}

// ---------------------------------------------------------------------------
// Kernel 4: fused output — r hoisted out of the MMA.
//   per i:  t[d,hw] = sum_j V[d,ij] * c[j,hw]      (pure MMA, B = c from smem)
//           acc[d,hw] += r[i,hw] * t[d,hw]         (FFMA on D-fragment)
//   out = acc + v
// CTA: 128 threads (4 warps), hw tile 128, smem 53KB -> 4 CTA/SM.
// ---------------------------------------------------------------------------
#define FO_CS  (128 * 68)      // c tile floats
#define FO_VP  (32 * 68)       // one V panel
#define FO_RS  128
#define FO_SMEM_FLOATS (FO_CS + 2 * FO_VP + 2 * FO_RS)
#define FO_SMEM_BYTES  (FO_SMEM_FLOATS * 4)

__global__ void __launch_bounds__(128, 4) fused_out_mma(float* __restrict__ out)
{
    extern __shared__ float sm[];
    float* cs = sm;                       // [128][68]  (tf32-rounded)
    float* Vp = sm + FO_CS;               // [2][32][68] (tf32-rounded)
    float* rs = sm + FO_CS + 2 * FO_VP;   // [2][128]    (fp32)

    const int hw0 = blockIdx.x * 128;
    const int bh  = blockIdx.y;
    const int b   = bh >> 3, H = bh & 7;
    const float* vbase = P_g + (b * OC + H * 160 + 128) * HW;
    const float* rbase = R_g + bh * (64 * HW);
    const float* cbase = C_g + bh * (64 * HW);
    const int tid  = threadIdx.x;
    const int wid  = tid >> 5;
    const int lane = tid & 31;
    const int mrow = lane >> 2;   // 0..7
    const int kcol = lane & 3;    // 0..3

    // stage c tile (tf32-rounded): cs[m][j] = c[j][hw0+m]
    for (int f = tid; f < 8192; f += 128) {
        int j = f >> 7, m = f & 127;
        cs[m * 68 + j] = f2tf32f(cbase[j * HW + hw0 + m]);
    }
    // stage V panel + r row for i = 0 into buffer 0
    {
        #pragma unroll
        for (int q = 0; q < 16; q++) {
            int f = tid + q * 128;
            int d = f >> 6, j = f & 63;
            Vp[d * 68 + j] = f2tf32f(vbase[d * HW + j]);
        }
        rs[tid] = rbase[hw0 + tid];
    }

    float acc[2][4][4] = {};
    float pv[16], pr;

    for (int i = 0; i < 64; i++) {
        __syncthreads();
        const int cur = i & 1;
        if (i < 63) {
            const float* vsrc = vbase + (i + 1) * 64;
            #pragma unroll
            for (int q = 0; q < 16; q++) {
                int f = tid + q * 128;
                int d = f >> 6, j = f & 63;
                pv[q] = vsrc[d * HW + j];
            }
            pr = rbase[(i + 1) * HW + hw0 + tid];
        }
        const float* vp = Vp + cur * FO_VP;
        const float* rr = rs + cur * FO_RS;

        // t = V_i @ c   (fresh accumulator per i)
        float t[2][4][4];
        #pragma unroll
        for (int jc = 0; jc < 8; jc++) {
            uint32_t a[2][4];
            #pragma unroll
            for (int ms = 0; ms < 2; ms++) {
                int d0 = ms * 16 + mrow;
                a[ms][0] = __float_as_uint(vp[d0 * 68 + jc * 8 + kcol]);
                a[ms][1] = __float_as_uint(vp[(d0 + 8) * 68 + jc * 8 + kcol]);
                a[ms][2] = __float_as_uint(vp[d0 * 68 + jc * 8 + 4 + kcol]);
                a[ms][3] = __float_as_uint(vp[(d0 + 8) * 68 + jc * 8 + 4 + kcol]);
            }
            #pragma unroll
            for (int ns = 0; ns < 4; ns++) {
                int hwl = wid * 32 + ns * 8 + mrow;
                uint32_t b0 = __float_as_uint(cs[hwl * 68 + jc * 8 + kcol]);
                uint32_t b1 = __float_as_uint(cs[hwl * 68 + jc * 8 + 4 + kcol]);
                if (jc == 0) {
                    mma16n8k8_z(t[0][ns], a[0], b0, b1);
                    mma16n8k8_z(t[1][ns], a[1], b0, b1);
                } else {
                    mma16n8k8(t[0][ns], a[0], b0, b1);
                    mma16n8k8(t[1][ns], a[1], b0, b1);
                }
            }
        }
        // acc += r[i, col] * t  (fragment cols are 2*kcol, 2*kcol+1)
        #pragma unroll
        for (int ns = 0; ns < 4; ns++) {
            int col0 = wid * 32 + ns * 8 + 2 * kcol;
            float2 rv2 = *(const float2*)&rr[col0];
            #pragma unroll
            for (int ms = 0; ms < 2; ms++) {
                acc[ms][ns][0] += rv2.x * t[ms][ns][0];
                acc[ms][ns][1] += rv2.y * t[ms][ns][1];
                acc[ms][ns][2] += rv2.x * t[ms][ns][2];
                acc[ms][ns][3] += rv2.y * t[ms][ns][3];
            }
        }
        if (i < 63) {
            float* vn = Vp + (1 - cur) * FO_VP;
            float* rn = rs + (1 - cur) * FO_RS;
            #pragma unroll
            for (int q = 0; q < 16; q++) {
                int f = tid + q * 128;
                int d = f >> 6, j = f & 63;
                vn[d * 68 + j] = f2tf32f(pv[q]);
            }
            rn[tid] = pr;
        }
    }

    // epilogue: out[d][hw] = acc + v
    float* ob = out + (b * 256 + H * 32) * HW;
    #pragma unroll
    for (int ms = 0; ms < 2; ms++) {
        #pragma unroll
        for (int ns = 0; ns < 4; ns++) {
            int d0  = ms * 16 + mrow;
            int col = hw0 + wid * 32 + ns * 8 + 2 * kcol;
            float2 v0 = *(const float2*)&vbase[d0 * HW + col];
            float2 v1 = *(const float2*)&vbase[(d0 + 8) * HW + col];
            *(float2*)&ob[d0 * HW + col] =
                make_float2(acc[ms][ns][0] + v0.x, acc[ms][ns][1] + v0.y);
            *(float2*)&ob[(d0 + 8) * HW + col] =
                make_float2(acc[ms][ns][2] + v1.x, acc[ms][ns][3] + v1.y);
        }
    }
}

// ---------------------------------------------------------------------------
extern "C" void kernel_launch(void* const* d_in, const int* in_sizes, int n_in,
                              void* d_out, int out_size)
{
    const float* x = (const float*)d_in[0];
    const float* w = (const float*)d_in[1];
    if (n_in >= 2 && in_sizes[0] == 327680 && in_sizes[1] == 2097152) {
        const float* t = x; x = w; w = t;
    }
    float* out = (float*)d_out;

    static int attr_set = 0;
    if (!attr_set) {
        cudaFuncSetAttribute(proj_mma, cudaFuncAttributeMaxDynamicSharedMemorySize,
                             PJ_SMEM_BYTES);
        cudaFuncSetAttribute(row_attn4, cudaFuncAttributeMaxDynamicSharedMemorySize,
                             RA_SMEM_BYTES);
        cudaFuncSetAttribute(fused_out_mma, cudaFuncAttributeMaxDynamicSharedMemorySize,
                             FO_SMEM_BYTES);
        attr_set = 1;
    }

    dim3 g1(32, 10, 2);
    proj_mma<<<g1, 256, PJ_SMEM_BYTES>>>(x, w);

    dim3 g2r(16, 16);
    row_attn4<<<g2r, 256, RA_SMEM_BYTES>>>();
    dim3 g2c(64, 16);
    col_attn_kernel<<<g2c, 256>>>();

    dim3 g4(32, 16);
    fused_out_mma<<<g4, 128, FO_SMEM_BYTES>>>(out);
}

// round 8
// speedup vs baseline: 3.2234x; 1.0541x over previous
#include <cuda_runtime.h>
#include <cstdint>

#define NHh 8
#define Dm 256          // NH*HD
#define OC 1280         // NH*(4*KD+HD)
#define HW 4096
#define NB 2
#define SCALEF 0.17677669529663687f

// Scratch (device globals; no runtime allocation allowed)
__device__ float P_g[NB * OC * HW];            // [b][o][hw]
__device__ float R_g[NB * NHh * 64 * HW];      // [b][H][i][hw] row softmax
__device__ float C_g[NB * NHh * 64 * HW];      // [b][H][j][hw] col softmax

// ---------------------------------------------------------------------------
// helpers: tf32 rounding + mma.sync (sm_80+ PTX, works on plain sm_103 target)
// ---------------------------------------------------------------------------
__device__ __forceinline__ uint32_t f2tf32(float x) {
    uint32_t u;
    asm("cvt.rna.tf32.f32 %0, %1;" : "=r"(u) : "f"(x));
    return u;
}
__device__ __forceinline__ float f2tf32f(float x) {
    uint32_t u = f2tf32(x);
    return __uint_as_float(u);
}
__device__ __forceinline__ void mma16n8k8(float* d, const uint32_t* a,
                                          uint32_t b0, uint32_t b1) {
    asm volatile("mma.sync.aligned.m16n8k8.row.col.f32.tf32.tf32.f32 "
                 "{%0,%1,%2,%3}, {%4,%5,%6,%7}, {%8,%9}, {%0,%1,%2,%3};"
                 : "+f"(d[0]), "+f"(d[1]), "+f"(d[2]), "+f"(d[3])
                 : "r"(a[0]), "r"(a[1]), "r"(a[2]), "r"(a[3]), "r"(b0), "r"(b1));
}
// zero-C variant: D = A*B (fresh accumulator)
__device__ __forceinline__ void mma16n8k8_z(float* d, const uint32_t* a,
                                            uint32_t b0, uint32_t b1) {
    asm volatile("mma.sync.aligned.m16n8k8.row.col.f32.tf32.tf32.f32 "
                 "{%0,%1,%2,%3}, {%4,%5,%6,%7}, {%8,%9}, {%10,%10,%10,%10};"
                 : "=f"(d[0]), "=f"(d[1]), "=f"(d[2]), "=f"(d[3])
                 : "r"(a[0]), "r"(a[1]), "r"(a[2]), "r"(a[3]), "r"(b0), "r"(b1),
                   "f"(0.0f));
}

// ---------------------------------------------------------------------------
// Kernel 1: projection GEMM (tf32 mma.sync)  (unchanged)
// ---------------------------------------------------------------------------
#define PJ_AS  (128 * 36)
#define PJ_BS  (32 * 136)
#define PJ_SMEM_FLOATS (2 * PJ_AS + 2 * PJ_BS)
#define PJ_SMEM_BYTES  (PJ_SMEM_FLOATS * 4)

__global__ void __launch_bounds__(256, 2) proj_mma(const float* __restrict__ x,
                                                   const float* __restrict__ w)
{
    extern __shared__ float sm[];
    float* as = sm;                 // [2][128][36]
    float* bs = sm + 2 * PJ_AS;     // [2][32][136]

    const int b  = blockIdx.z;
    const int m0 = blockIdx.y * 128;
    const int n0 = blockIdx.x * 128;
    const int tid  = threadIdx.x;
    const int wid  = tid >> 5;
    const int lane = tid & 31;
    const int mrow = lane >> 2;
    const int kcol = lane & 3;
    const int wm = wid & 1;
    const int wn = wid >> 1;
    const float* xb = x + b * (Dm * HW);

    float acc[4][4][4] = {};
    float pa[16], pbr[16];

    #pragma unroll
    for (int q = 0; q < 16; q++) {
        int f = tid + q * 256;
        int o = f >> 5, c = f & 31;
        pa[q]  = w[(m0 + o) * Dm + c];
        int k = f >> 7, n = f & 127;
        pbr[q] = xb[k * HW + n0 + n];
    }
    #pragma unroll
    for (int q = 0; q < 16; q++) {
        int f = tid + q * 256;
        int o = f >> 5, c = f & 31;
        as[o * 36 + c] = f2tf32f(pa[q]);
        int k = f >> 7, n = f & 127;
        bs[k * 136 + n] = f2tf32f(pbr[q]);
    }

    for (int kt = 0; kt < 8; kt++) {
        __syncthreads();
        const int buf = kt & 1;
        if (kt < 7) {
            const int c0 = (kt + 1) * 32;
            #pragma unroll
            for (int q = 0; q < 16; q++) {
                int f = tid + q * 256;
                int o = f >> 5, c = f & 31;
                pa[q]  = w[(m0 + o) * Dm + c0 + c];
                int k = f >> 7, n = f & 127;
                pbr[q] = xb[(c0 + k) * HW + n0 + n];
            }
        }
        const float* ab = as + buf * PJ_AS;
        const float* bb = bs + buf * PJ_BS;
        #pragma unroll
        for (int k8 = 0; k8 < 4; k8++) {
            uint32_t a[4][4];
            #pragma unroll
            for (int msl = 0; msl < 4; msl++) {
                int r0 = wm * 64 + msl * 16 + mrow;
                a[msl][0] = __float_as_uint(ab[r0 * 36 + k8 * 8 + kcol]);
                a[msl][1] = __float_as_uint(ab[(r0 + 8) * 36 + k8 * 8 + kcol]);
                a[msl][2] = __float_as_uint(ab[r0 * 36 + k8 * 8 + 4 + kcol]);
                a[msl][3] = __float_as_uint(ab[(r0 + 8) * 36 + k8 * 8 + 4 + kcol]);
            }
            #pragma unroll
            for (int nsl = 0; nsl < 4; nsl++) {
                int ncol = wn * 32 + nsl * 8 + mrow;
                uint32_t b0 = __float_as_uint(bb[(k8 * 8 + kcol) * 136 + ncol]);
                uint32_t b1 = __float_as_uint(bb[(k8 * 8 + 4 + kcol) * 136 + ncol]);
                #pragma unroll
                for (int msl = 0; msl < 4; msl++)
                    mma16n8k8(acc[msl][nsl], a[msl], b0, b1);
            }
        }
        if (kt < 7) {
            float* an = as + (1 - buf) * PJ_AS;
            float* bn = bs + (1 - buf) * PJ_BS;
            #pragma unroll
            for (int q = 0; q < 16; q++) {
                int f = tid + q * 256;
                int o = f >> 5, c = f & 31;
                an[o * 36 + c] = f2tf32f(pa[q]);
                int k = f >> 7, n = f & 127;
                bn[k * 136 + n] = f2tf32f(pbr[q]);
            }
        }
    }

    float* pb = P_g + b * (OC * HW);
    #pragma unroll
    for (int msl = 0; msl < 4; msl++) {
        #pragma unroll
        for (int nsl = 0; nsl < 4; nsl++) {
            int r0 = m0 + wm * 64 + msl * 16 + mrow;
            int cn = n0 + wn * 32 + nsl * 8 + 2 * kcol;
            *(float2*)&pb[r0 * HW + cn] =
                make_float2(acc[msl][nsl][0], acc[msl][nsl][1]);
            *(float2*)&pb[(r0 + 8) * HW + cn] =
                make_float2(acc[msl][nsl][2], acc[msl][nsl][3]);
        }
    }
}

// ---------------------------------------------------------------------------
// Kernel 2: row attention, w-quad version (unchanged)
// ---------------------------------------------------------------------------
#define QSTR (32 * 65 + 1)
#define ASTR (64 * 65 + 1)
#define RA_SMEM_FLOATS (8 * QSTR)
#define RA_SMEM_BYTES  (RA_SMEM_FLOATS * 4)

__global__ void __launch_bounds__(256) row_attn4()
{
    extern __shared__ float smb[];
    float* q_s = smb;
    float* k_s = smb + 4 * QSTR;

    const int w0 = blockIdx.x * 4;
    const int bh = blockIdx.y;
    const int b  = bh >> 3, H = bh & 7;
    const float* qb = P_g + (b * OC + H * 160) * HW;
    const float* kb = qb + 32 * HW;
    const int tid = threadIdx.x;

    for (int e = tid; e < 8192; e += 256) {
        int ww = e & 3, i = (e >> 2) & 63, d = e >> 8;
        q_s[ww * QSTR + d * 65 + i] = qb[d * HW + i * 64 + w0 + ww];
        k_s[ww * QSTR + d * 65 + i] = kb[d * HW + i * 64 + w0 + ww];
    }
    __syncthreads();

    const int ww = tid >> 6;
    const int gt = tid & 63;
    const int ti = (gt >> 3) * 8;
    const int tj = (gt & 7) * 8;
    const float* qq = q_s + ww * QSTR;
    const float* kk = k_s + ww * QSTR;

    float acc[8][8] = {};
    #pragma unroll 4
    for (int d = 0; d < 32; d++) {
        float qv[8], kv[8];
        #pragma unroll
        for (int u = 0; u < 8; u++) qv[u] = qq[d * 65 + ti + u];
        #pragma unroll
        for (int v = 0; v < 8; v++) kv[v] = kk[d * 65 + tj + v];
        #pragma unroll
        for (int u = 0; u < 8; u++)
            #pragma unroll
            for (int v = 0; v < 8; v++)
                acc[u][v] += qv[u] * kv[v];
    }
    __syncthreads();

    float* a_s = smb;
    #pragma unroll
    for (int u = 0; u < 8; u++)
        #pragma unroll
        for (int v = 0; v < 8; v++)
            a_s[ww * ASTR + (ti + u) * 65 + (tj + v)] = acc[u][v] * SCALEF;
    __syncthreads();

    {
        const int ww2 = tid & 3;
        const int j   = tid >> 2;
        float* col = a_s + ww2 * ASTR + j;
        float mx = -1e30f;
        #pragma unroll 8
        for (int i = 0; i < 64; i++) mx = fmaxf(mx, col[i * 65]);
        float s = 0.f;
        #pragma unroll 8
        for (int i = 0; i < 64; i++) {
            float e = __expf(col[i * 65] - mx);
            col[i * 65] = e;
            s += e;
        }
        float inv = 1.f / s;
        float* rb = R_g + bh * (64 * HW) + j * 64 + w0 + ww2;
        #pragma unroll 8
        for (int i = 0; i < 64; i++)
            rb[i * HW] = col[i * 65] * inv;
    }
}

// ---------------------------------------------------------------------------
// Kernel 3: column attention (unchanged)
// ---------------------------------------------------------------------------
__global__ void col_attn_kernel()
{
    int h  = blockIdx.x;
    int bh = blockIdx.y;
    int b  = bh >> 3, H = bh & 7;
    const float* base = P_g + (b * OC + H * 160) * HW;
    int tid = threadIdx.x;

    __shared__ float q_s[32][64];
    __shared__ float k_s[32][64];
    __shared__ float a_s[64][68];

    for (int f = tid; f < 2048; f += 256) {
        int d = f >> 6, i = f & 63;
        q_s[d][i] = base[(64 + d) * HW + h * 64 + i];
        k_s[d][i] = base[(96 + d) * HW + h * 64 + i];
    }
    __syncthreads();

    int ti = (tid >> 4) * 4;
    int tj = (tid & 15) * 4;
    float acc[4][4] = {};
    #pragma unroll
    for (int d = 0; d < 32; d++) {
        float4 av = *(const float4*)&q_s[d][ti];
        float4 bv = *(const float4*)&k_s[d][tj];
        float avv[4] = {av.x, av.y, av.z, av.w};
        float bvv[4] = {bv.x, bv.y, bv.z, bv.w};
        #pragma unroll
        for (int u = 0; u < 4; u++)
            #pragma unroll
            for (int v2 = 0; v2 < 4; v2++)
                acc[u][v2] += avv[u] * bvv[v2];
    }
    #pragma unroll
    for (int u = 0; u < 4; u++)
        #pragma unroll
        for (int v2 = 0; v2 < 4; v2++)
            a_s[ti + u][tj + v2] = acc[u][v2] * SCALEF;
    __syncthreads();

    if (tid < 64) {
        int j = tid;
        float mx = -1e30f;
        #pragma unroll 8
        for (int i = 0; i < 64; i++) mx = fmaxf(mx, a_s[i][j]);
        float s = 0.f;
        #pragma unroll 8
        for (int i = 0; i < 64; i++) {
            float e = __expf(a_s[i][j] - mx);
            a_s[i][j] = e;
            s += e;
        }
        float inv = 1.f / s;
        float* cb = C_g + bh * (64 * HW);
        #pragma unroll 8
        for (int i = 0; i < 64; i++)
            cb[i * HW + h * 64 + j] = a_s[i][j] * inv;
    }
}

// ---------------------------------------------------------------------------
// Kernel 4: fused output — fragment-layout smem, LDS.128 operand fetch.
//   per i:  t[d,hw] = sum_j V[d,ij] * c[j,hw]   (MMA; A,B pre-staged in exact
//           fragment order -> 1 LDS.128 per fragment)
//           acc[d,hw] += r[i,hw] * t[d,hw]
//   out = acc + v
// V fragment block fb = jc*2+ms (16 blocks, pitch 140 floats).
// c fragment block (nb*4+jcp) (64 blocks, pitch 132 floats), staged once;
//   uint4 = {b0(jc even), b1(jc even), b0(jc odd), b1(jc odd)}.
// ---------------------------------------------------------------------------
#define FO_CF   (64 * 132)          // 8448 floats (33.8 KB)
#define FO_VF   (16 * 140)          // 2240 floats per buffer
#define FO_RS   128
#define FO_SMEM_FLOATS (FO_CF + 2 * FO_VF + 2 * FO_RS)
#define FO_SMEM_BYTES  (FO_SMEM_FLOATS * 4)   // 52736 B -> 4 CTA/SM

__global__ void __launch_bounds__(128, 4) fused_out_mma(float* __restrict__ out)
{
    extern __shared__ float sm[];
    float* cf = sm;                       // c fragments (tf32)
    float* Vf = sm + FO_CF;               // [2] V fragments (tf32)
    float* rs = sm + FO_CF + 2 * FO_VF;   // [2][128] r (fp32)

    const int hw0 = blockIdx.x * 128;
    const int bh  = blockIdx.y;
    const int b   = bh >> 3, H = bh & 7;
    const float* vbase = P_g + (b * OC + H * 160 + 128) * HW;
    const float* rbase = R_g + bh * (64 * HW);
    const float* cbase = C_g + bh * (64 * HW);
    const int tid  = threadIdx.x;
    const int wid  = tid >> 5;
    const int lane = tid & 31;
    const int mrow = lane >> 2;   // 0..7
    const int kcol = lane & 3;    // 0..3

    // stage c fragments (once): value c[j][hw0+m]
    for (int f = tid; f < 8192; f += 128) {
        int j = f >> 7, m = f & 127;                 // m coalesced within warp
        int nb   = m >> 3;
        int jcp  = j >> 4;
        int ln   = (m & 7) * 4 + (j & 3);
        int reg  = ((j >> 3) & 1) * 2 + ((j >> 2) & 1);
        cf[(nb * 4 + jcp) * 132 + ln * 4 + reg] = f2tf32f(cbase[j * HW + hw0 + m]);
    }
    // stage V fragments for i = 0 into buffer 0, and r row
    #pragma unroll
    for (int q = 0; q < 16; q++) {
        int f = tid + q * 128;
        int d = f >> 6, j = f & 63;
        float val = f2tf32f(vbase[d * HW + j]);
        int fb  = (j >> 3) * 2 + (d >> 4);
        int ln  = (d & 7) * 4 + (j & 3);
        int reg = ((d >> 3) & 1) + 2 * ((j >> 2) & 1);
        Vf[fb * 140 + ln * 4 + reg] = val;
    }
    rs[tid] = rbase[hw0 + tid];

    const uint4* cf4 = (const uint4*)cf;
    const int nbb = wid * 4;              // this warp's hw-block base

    float acc[2][4][4] = {};
    float pv[16], pr;

    for (int i = 0; i < 64; i++) {
        __syncthreads();
        const int cur = i & 1;
        if (i < 63) {
            const float* vsrc = vbase + (i + 1) * 64;
            #pragma unroll
            for (int q = 0; q < 16; q++) {
                int f = tid + q * 128;
                int d = f >> 6, j = f & 63;
                pv[q] = vsrc[d * HW + j];
            }
            pr = rbase[(i + 1) * HW + hw0 + tid];
        }
        const uint4* vp4 = (const uint4*)(Vf + cur * FO_VF);
        const float* rr  = rs + cur * FO_RS;

        // t = V_i @ c
        float t[2][4][4];
        uint4 bv[4];
        #pragma unroll
        for (int jc = 0; jc < 8; jc++) {
            uint4 av0 = vp4[(jc * 2 + 0) * 35 + lane];
            uint4 av1 = vp4[(jc * 2 + 1) * 35 + lane];
            uint32_t a0[4] = {av0.x, av0.y, av0.z, av0.w};
            uint32_t a1[4] = {av1.x, av1.y, av1.z, av1.w};
            if ((jc & 1) == 0) {
                #pragma unroll
                for (int ns = 0; ns < 4; ns++)
                    bv[ns] = cf4[((nbb + ns) * 4 + (jc >> 1)) * 33 + lane];
            }
            #pragma unroll
            for (int ns = 0; ns < 4; ns++) {
                uint32_t b0 = (jc & 1) ? bv[ns].z : bv[ns].x;
                uint32_t b1 = (jc & 1) ? bv[ns].w : bv[ns].y;
                if (jc == 0) {
                    mma16n8k8_z(t[0][ns], a0, b0, b1);
                    mma16n8k8_z(t[1][ns], a1, b0, b1);
                } else {
                    mma16n8k8(t[0][ns], a0, b0, b1);
                    mma16n8k8(t[1][ns], a1, b0, b1);
                }
            }
        }
        // acc += r[i, col] * t  (fragment cols are 2*kcol, 2*kcol+1)
        #pragma unroll
        for (int ns = 0; ns < 4; ns++) {
            int col0 = wid * 32 + ns * 8 + 2 * kcol;
            float2 rv2 = *(const float2*)&rr[col0];
            #pragma unroll
            for (int ms = 0; ms < 2; ms++) {
                acc[ms][ns][0] += rv2.x * t[ms][ns][0];
                acc[ms][ns][1] += rv2.y * t[ms][ns][1];
                acc[ms][ns][2] += rv2.x * t[ms][ns][2];
                acc[ms][ns][3] += rv2.y * t[ms][ns][3];
            }
        }
        // scatter prefetched V panel into other buffer (fragment order)
        if (i < 63) {
            float* vn = Vf + (1 - cur) * FO_VF;
            float* rn = rs + (1 - cur) * FO_RS;
            #pragma unroll
            for (int q = 0; q < 16; q++) {
                int f = tid + q * 128;
                int d = f >> 6, j = f & 63;
                int fb  = (j >> 3) * 2 + (d >> 4);
                int ln  = (d & 7) * 4 + (j & 3);
                int reg = ((d >> 3) & 1) + 2 * ((j >> 2) & 1);
                vn[fb * 140 + ln * 4 + reg] = f2tf32f(pv[q]);
            }
            rn[tid] = pr;
        }
    }

    // epilogue: out[d][hw] = acc + v
    float* ob = out + (b * 256 + H * 32) * HW;
    #pragma unroll
    for (int ms = 0; ms < 2; ms++) {
        #pragma unroll
        for (int ns = 0; ns < 4; ns++) {
            int d0  = ms * 16 + mrow;
            int col = hw0 + wid * 32 + ns * 8 + 2 * kcol;
            float2 v0 = *(const float2*)&vbase[d0 * HW + col];
            float2 v1 = *(const float2*)&vbase[(d0 + 8) * HW + col];
            *(float2*)&ob[d0 * HW + col] =
                make_float2(acc[ms][ns][0] + v0.x, acc[ms][ns][1] + v0.y);
            *(float2*)&ob[(d0 + 8) * HW + col] =
                make_float2(acc[ms][ns][2] + v1.x, acc[ms][ns][3] + v1.y);
        }
    }
}

// ---------------------------------------------------------------------------
extern "C" void kernel_launch(void* const* d_in, const int* in_sizes, int n_in,
                              void* d_out, int out_size)
{
    const float* x = (const float*)d_in[0];
    const float* w = (const float*)d_in[1];
    if (n_in >= 2 && in_sizes[0] == 327680 && in_sizes[1] == 2097152) {
        const float* t = x; x = w; w = t;
    }
    float* out = (float*)d_out;

    static int attr_set = 0;
    if (!attr_set) {
        cudaFuncSetAttribute(proj_mma, cudaFuncAttributeMaxDynamicSharedMemorySize,
                             PJ_SMEM_BYTES);
        cudaFuncSetAttribute(row_attn4, cudaFuncAttributeMaxDynamicSharedMemorySize,
                             RA_SMEM_BYTES);
        cudaFuncSetAttribute(fused_out_mma, cudaFuncAttributeMaxDynamicSharedMemorySize,
                             FO_SMEM_BYTES);
        attr_set = 1;
    }

    dim3 g1(32, 10, 2);
    proj_mma<<<g1, 256, PJ_SMEM_BYTES>>>(x, w);

    dim3 g2r(16, 16);
    row_attn4<<<g2r, 256, RA_SMEM_BYTES>>>();
    dim3 g2c(64, 16);
    col_attn_kernel<<<g2c, 256>>>();

    dim3 g4(32, 16);
    fused_out_mma<<<g4, 128, FO_SMEM_BYTES>>>(out);
}

// round 9
// speedup vs baseline: 3.4102x; 1.0580x over previous
#include <cuda_runtime.h>
#include <cstdint>

#define NHh 8
#define Dm 256          // NH*HD
#define OC 1280         // NH*(4*KD+HD)
#define HW 4096
#define NB 2
#define SCALEF 0.17677669529663687f

// Scratch (device globals; no runtime allocation allowed)
__device__ float P_g[NB * OC * HW];            // [b][o][hw]
__device__ float R_g[NB * NHh * 64 * HW];      // [b][H][i][hw] row softmax
__device__ float C_g[NB * NHh * 64 * HW];      // [b][H][j][hw] col softmax

// ---------------------------------------------------------------------------
// helpers: tf32 rounding + mma.sync (sm_80+ PTX, works on plain sm_103 target)
// ---------------------------------------------------------------------------
__device__ __forceinline__ uint32_t f2tf32(float x) {
    uint32_t u;
    asm("cvt.rna.tf32.f32 %0, %1;" : "=r"(u) : "f"(x));
    return u;
}
__device__ __forceinline__ float f2tf32f(float x) {
    uint32_t u = f2tf32(x);
    return __uint_as_float(u);
}
__device__ __forceinline__ void mma16n8k8(float* d, const uint32_t* a,
                                          uint32_t b0, uint32_t b1) {
    asm volatile("mma.sync.aligned.m16n8k8.row.col.f32.tf32.tf32.f32 "
                 "{%0,%1,%2,%3}, {%4,%5,%6,%7}, {%8,%9}, {%0,%1,%2,%3};"
                 : "+f"(d[0]), "+f"(d[1]), "+f"(d[2]), "+f"(d[3])
                 : "r"(a[0]), "r"(a[1]), "r"(a[2]), "r"(a[3]), "r"(b0), "r"(b1));
}
// zero-C variant: D = A*B (fresh accumulator)
__device__ __forceinline__ void mma16n8k8_z(float* d, const uint32_t* a,
                                            uint32_t b0, uint32_t b1) {
    asm volatile("mma.sync.aligned.m16n8k8.row.col.f32.tf32.tf32.f32 "
                 "{%0,%1,%2,%3}, {%4,%5,%6,%7}, {%8,%9}, {%10,%10,%10,%10};"
                 : "=f"(d[0]), "=f"(d[1]), "=f"(d[2]), "=f"(d[3])
                 : "r"(a[0]), "r"(a[1]), "r"(a[2]), "r"(a[3]), "r"(b0), "r"(b1),
                   "f"(0.0f));
}

// ---------------------------------------------------------------------------
// Kernel 1: projection GEMM (tf32 mma.sync)  (unchanged)
// ---------------------------------------------------------------------------
#define PJ_AS  (128 * 36)
#define PJ_BS  (32 * 136)
#define PJ_SMEM_FLOATS (2 * PJ_AS + 2 * PJ_BS)
#define PJ_SMEM_BYTES  (PJ_SMEM_FLOATS * 4)

__global__ void __launch_bounds__(256, 2) proj_mma(const float* __restrict__ x,
                                                   const float* __restrict__ w)
{
    extern __shared__ float sm[];
    float* as = sm;                 // [2][128][36]
    float* bs = sm + 2 * PJ_AS;     // [2][32][136]

    const int b  = blockIdx.z;
    const int m0 = blockIdx.y * 128;
    const int n0 = blockIdx.x * 128;
    const int tid  = threadIdx.x;
    const int wid  = tid >> 5;
    const int lane = tid & 31;
    const int mrow = lane >> 2;
    const int kcol = lane & 3;
    const int wm = wid & 1;
    const int wn = wid >> 1;
    const float* xb = x + b * (Dm * HW);

    float acc[4][4][4] = {};
    float pa[16], pbr[16];

    #pragma unroll
    for (int q = 0; q < 16; q++) {
        int f = tid + q * 256;
        int o = f >> 5, c = f & 31;
        pa[q]  = w[(m0 + o) * Dm + c];
        int k = f >> 7, n = f & 127;
        pbr[q] = xb[k * HW + n0 + n];
    }
    #pragma unroll
    for (int q = 0; q < 16; q++) {
        int f = tid + q * 256;
        int o = f >> 5, c = f & 31;
        as[o * 36 + c] = f2tf32f(pa[q]);
        int k = f >> 7, n = f & 127;
        bs[k * 136 + n] = f2tf32f(pbr[q]);
    }

    for (int kt = 0; kt < 8; kt++) {
        __syncthreads();
        const int buf = kt & 1;
        if (kt < 7) {
            const int c0 = (kt + 1) * 32;
            #pragma unroll
            for (int q = 0; q < 16; q++) {
                int f = tid + q * 256;
                int o = f >> 5, c = f & 31;
                pa[q]  = w[(m0 + o) * Dm + c0 + c];
                int k = f >> 7, n = f & 127;
                pbr[q] = xb[(c0 + k) * HW + n0 + n];
            }
        }
        const float* ab = as + buf * PJ_AS;
        const float* bb = bs + buf * PJ_BS;
        #pragma unroll
        for (int k8 = 0; k8 < 4; k8++) {
            uint32_t a[4][4];
            #pragma unroll
            for (int msl = 0; msl < 4; msl++) {
                int r0 = wm * 64 + msl * 16 + mrow;
                a[msl][0] = __float_as_uint(ab[r0 * 36 + k8 * 8 + kcol]);
                a[msl][1] = __float_as_uint(ab[(r0 + 8) * 36 + k8 * 8 + kcol]);
                a[msl][2] = __float_as_uint(ab[r0 * 36 + k8 * 8 + 4 + kcol]);
                a[msl][3] = __float_as_uint(ab[(r0 + 8) * 36 + k8 * 8 + 4 + kcol]);
            }
            #pragma unroll
            for (int nsl = 0; nsl < 4; nsl++) {
                int ncol = wn * 32 + nsl * 8 + mrow;
                uint32_t b0 = __float_as_uint(bb[(k8 * 8 + kcol) * 136 + ncol]);
                uint32_t b1 = __float_as_uint(bb[(k8 * 8 + 4 + kcol) * 136 + ncol]);
                #pragma unroll
                for (int msl = 0; msl < 4; msl++)
                    mma16n8k8(acc[msl][nsl], a[msl], b0, b1);
            }
        }
        if (kt < 7) {
            float* an = as + (1 - buf) * PJ_AS;
            float* bn = bs + (1 - buf) * PJ_BS;
            #pragma unroll
            for (int q = 0; q < 16; q++) {
                int f = tid + q * 256;
                int o = f >> 5, c = f & 31;
                an[o * 36 + c] = f2tf32f(pa[q]);
                int k = f >> 7, n = f & 127;
                bn[k * 136 + n] = f2tf32f(pbr[q]);
            }
        }
    }

    float* pb = P_g + b * (OC * HW);
    #pragma unroll
    for (int msl = 0; msl < 4; msl++) {
        #pragma unroll
        for (int nsl = 0; nsl < 4; nsl++) {
            int r0 = m0 + wm * 64 + msl * 16 + mrow;
            int cn = n0 + wn * 32 + nsl * 8 + 2 * kcol;
            *(float2*)&pb[r0 * HW + cn] =
                make_float2(acc[msl][nsl][0], acc[msl][nsl][1]);
            *(float2*)&pb[(r0 + 8) * HW + cn] =
                make_float2(acc[msl][nsl][2], acc[msl][nsl][3]);
        }
    }
}

// ---------------------------------------------------------------------------
// Kernel 2: row attention, w-quad version (unchanged)
// ---------------------------------------------------------------------------
#define QSTR (32 * 65 + 1)
#define ASTR (64 * 65 + 1)
#define RA_SMEM_FLOATS (8 * QSTR)
#define RA_SMEM_BYTES  (RA_SMEM_FLOATS * 4)

__global__ void __launch_bounds__(256) row_attn4()
{
    extern __shared__ float smb[];
    float* q_s = smb;
    float* k_s = smb + 4 * QSTR;

    const int w0 = blockIdx.x * 4;
    const int bh = blockIdx.y;
    const int b  = bh >> 3, H = bh & 7;
    const float* qb = P_g + (b * OC + H * 160) * HW;
    const float* kb = qb + 32 * HW;
    const int tid = threadIdx.x;

    for (int e = tid; e < 8192; e += 256) {
        int ww = e & 3, i = (e >> 2) & 63, d = e >> 8;
        q_s[ww * QSTR + d * 65 + i] = qb[d * HW + i * 64 + w0 + ww];
        k_s[ww * QSTR + d * 65 + i] = kb[d * HW + i * 64 + w0 + ww];
    }
    __syncthreads();

    const int ww = tid >> 6;
    const int gt = tid & 63;
    const int ti = (gt >> 3) * 8;
    const int tj = (gt & 7) * 8;
    const float* qq = q_s + ww * QSTR;
    const float* kk = k_s + ww * QSTR;

    float acc[8][8] = {};
    #pragma unroll 4
    for (int d = 0; d < 32; d++) {
        float qv[8], kv[8];
        #pragma unroll
        for (int u = 0; u < 8; u++) qv[u] = qq[d * 65 + ti + u];
        #pragma unroll
        for (int v = 0; v < 8; v++) kv[v] = kk[d * 65 + tj + v];
        #pragma unroll
        for (int u = 0; u < 8; u++)
            #pragma unroll
            for (int v = 0; v < 8; v++)
                acc[u][v] += qv[u] * kv[v];
    }
    __syncthreads();

    float* a_s = smb;
    #pragma unroll
    for (int u = 0; u < 8; u++)
        #pragma unroll
        for (int v = 0; v < 8; v++)
            a_s[ww * ASTR + (ti + u) * 65 + (tj + v)] = acc[u][v] * SCALEF;
    __syncthreads();

    {
        const int ww2 = tid & 3;
        const int j   = tid >> 2;
        float* col = a_s + ww2 * ASTR + j;
        float mx = -1e30f;
        #pragma unroll 8
        for (int i = 0; i < 64; i++) mx = fmaxf(mx, col[i * 65]);
        float s = 0.f;
        #pragma unroll 8
        for (int i = 0; i < 64; i++) {
            float e = __expf(col[i * 65] - mx);
            col[i * 65] = e;
            s += e;
        }
        float inv = 1.f / s;
        float* rb = R_g + bh * (64 * HW) + j * 64 + w0 + ww2;
        #pragma unroll 8
        for (int i = 0; i < 64; i++)
            rb[i * HW] = col[i * 65] * inv;
    }
}

// ---------------------------------------------------------------------------
// Kernel 3: column attention (unchanged)
// ---------------------------------------------------------------------------
__global__ void col_attn_kernel()
{
    int h  = blockIdx.x;
    int bh = blockIdx.y;
    int b  = bh >> 3, H = bh & 7;
    const float* base = P_g + (b * OC + H * 160) * HW;
    int tid = threadIdx.x;

    __shared__ float q_s[32][64];
    __shared__ float k_s[32][64];
    __shared__ float a_s[64][68];

    for (int f = tid; f < 2048; f += 256) {
        int d = f >> 6, i = f & 63;
        q_s[d][i] = base[(64 + d) * HW + h * 64 + i];
        k_s[d][i] = base[(96 + d) * HW + h * 64 + i];
    }
    __syncthreads();

    int ti = (tid >> 4) * 4;
    int tj = (tid & 15) * 4;
    float acc[4][4] = {};
    #pragma unroll
    for (int d = 0; d < 32; d++) {
        float4 av = *(const float4*)&q_s[d][ti];
        float4 bv = *(const float4*)&k_s[d][tj];
        float avv[4] = {av.x, av.y, av.z, av.w};
        float bvv[4] = {bv.x, bv.y, bv.z, bv.w};
        #pragma unroll
        for (int u = 0; u < 4; u++)
            #pragma unroll
            for (int v2 = 0; v2 < 4; v2++)
                acc[u][v2] += avv[u] * bvv[v2];
    }
    #pragma unroll
    for (int u = 0; u < 4; u++)
        #pragma unroll
        for (int v2 = 0; v2 < 4; v2++)
            a_s[ti + u][tj + v2] = acc[u][v2] * SCALEF;
    __syncthreads();

    if (tid < 64) {
        int j = tid;
        float mx = -1e30f;
        #pragma unroll 8
        for (int i = 0; i < 64; i++) mx = fmaxf(mx, a_s[i][j]);
        float s = 0.f;
        #pragma unroll 8
        for (int i = 0; i < 64; i++) {
            float e = __expf(a_s[i][j] - mx);
            a_s[i][j] = e;
            s += e;
        }
        float inv = 1.f / s;
        float* cb = C_g + bh * (64 * HW);
        #pragma unroll 8
        for (int i = 0; i < 64; i++)
            cb[i * HW + h * 64 + j] = a_s[i][j] * inv;
    }
}

// ---------------------------------------------------------------------------
// Kernel 4: fused output — wide warps (64 hw per warp) to halve A replication
// and staging per hw.  CTA: 128 threads / 4 warps / 256 hw tile.
//   per i:  t[d,hw] = sum_j V[d,ij] * c[j,hw]   (fragment-layout smem,
//           LDS.128 operand fetch)
//           acc[d,hw] += r[i,hw] * t[d,hw]
//   out = acc + v
// ---------------------------------------------------------------------------
#define FO_CF   (128 * 132)         // 128 c-fragment blocks (nb 0..31 x jcp 0..3)
#define FO_VF   (16 * 140)          // V fragments per buffer
#define FO_RS   256
#define FO_SMEM_FLOATS (FO_CF + 2 * FO_VF + 2 * FO_RS)
#define FO_SMEM_BYTES  (FO_SMEM_FLOATS * 4)   // 87552 B -> 2 CTA/SM

__global__ void __launch_bounds__(128, 2) fused_out_mma(float* __restrict__ out)
{
    extern __shared__ float sm[];
    float* cf = sm;                       // c fragments (tf32)
    float* Vf = sm + FO_CF;               // [2] V fragments (tf32)
    float* rs = sm + FO_CF + 2 * FO_VF;   // [2][256] r (fp32)

    const int hw0 = blockIdx.x * 256;
    const int bh  = blockIdx.y;
    const int b   = bh >> 3, H = bh & 7;
    const float* vbase = P_g + (b * OC + H * 160 + 128) * HW;
    const float* rbase = R_g + bh * (64 * HW);
    const float* cbase = C_g + bh * (64 * HW);
    const int tid  = threadIdx.x;
    const int wid  = tid >> 5;
    const int lane = tid & 31;
    const int mrow = lane >> 2;   // 0..7
    const int kcol = lane & 3;    // 0..3

    // stage c fragments (once): value c[j][hw0+m], m in [0,256)
    for (int f = tid; f < 16384; f += 128) {
        int j = f >> 8, m = f & 255;                 // m coalesced within warp
        int nb   = m >> 3;                           // 0..31
        int jcp  = j >> 4;                           // 0..3
        int ln   = (m & 7) * 4 + (j & 3);
        int reg  = ((j >> 3) & 1) * 2 + ((j >> 2) & 1);
        cf[(nb * 4 + jcp) * 132 + ln * 4 + reg] = f2tf32f(cbase[j * HW + hw0 + m]);
    }
    // stage V fragments for i = 0 into buffer 0, and r row (256 entries)
    #pragma unroll
    for (int q = 0; q < 16; q++) {
        int f = tid + q * 128;
        int d = f >> 6, j = f & 63;
        float val = f2tf32f(vbase[d * HW + j]);
        int fb  = (j >> 3) * 2 + (d >> 4);
        int ln  = (d & 7) * 4 + (j & 3);
        int reg = ((d >> 3) & 1) + 2 * ((j >> 2) & 1);
        Vf[fb * 140 + ln * 4 + reg] = val;
    }
    rs[tid]       = rbase[hw0 + tid];
    rs[tid + 128] = rbase[hw0 + tid + 128];

    const uint4* cf4 = (const uint4*)cf;
    const int nbb = wid * 8;              // this warp's hw-block base (8 blocks)

    float acc[2][8][4] = {};
    float pv[16], pr0, pr1;

    for (int i = 0; i < 64; i++) {
        __syncthreads();
        const int cur = i & 1;
        if (i < 63) {
            const float* vsrc = vbase + (i + 1) * 64;
            #pragma unroll
            for (int q = 0; q < 16; q++) {
                int f = tid + q * 128;
                int d = f >> 6, j = f & 63;
                pv[q] = vsrc[d * HW + j];
            }
            pr0 = rbase[(i + 1) * HW + hw0 + tid];
            pr1 = rbase[(i + 1) * HW + hw0 + tid + 128];
        }
        const uint4* vp4 = (const uint4*)(Vf + cur * FO_VF);
        const float* rr  = rs + cur * FO_RS;

        // t = V_i @ c
        float t[2][8][4];
        uint4 bv[8];
        #pragma unroll
        for (int jc = 0; jc < 8; jc++) {
            uint4 av0 = vp4[(jc * 2 + 0) * 35 + lane];
            uint4 av1 = vp4[(jc * 2 + 1) * 35 + lane];
            uint32_t a0[4] = {av0.x, av0.y, av0.z, av0.w};
            uint32_t a1[4] = {av1.x, av1.y, av1.z, av1.w};
            if ((jc & 1) == 0) {
                #pragma unroll
                for (int ns = 0; ns < 8; ns++)
                    bv[ns] = cf4[((nbb + ns) * 4 + (jc >> 1)) * 33 + lane];
            }
            #pragma unroll
            for (int ns = 0; ns < 8; ns++) {
                uint32_t b0 = (jc & 1) ? bv[ns].z : bv[ns].x;
                uint32_t b1 = (jc & 1) ? bv[ns].w : bv[ns].y;
                if (jc == 0) {
                    mma16n8k8_z(t[0][ns], a0, b0, b1);
                    mma16n8k8_z(t[1][ns], a1, b0, b1);
                } else {
                    mma16n8k8(t[0][ns], a0, b0, b1);
                    mma16n8k8(t[1][ns], a1, b0, b1);
                }
            }
        }
        // acc += r[i, col] * t  (fragment cols are 2*kcol, 2*kcol+1)
        #pragma unroll
        for (int ns = 0; ns < 8; ns++) {
            int col0 = wid * 64 + ns * 8 + 2 * kcol;
            float2 rv2 = *(const float2*)&rr[col0];
            #pragma unroll
            for (int ms = 0; ms < 2; ms++) {
                acc[ms][ns][0] += rv2.x * t[ms][ns][0];
                acc[ms][ns][1] += rv2.y * t[ms][ns][1];
                acc[ms][ns][2] += rv2.x * t[ms][ns][2];
                acc[ms][ns][3] += rv2.y * t[ms][ns][3];
            }
        }
        // scatter prefetched V panel into other buffer (fragment order)
        if (i < 63) {
            float* vn = Vf + (1 - cur) * FO_VF;
            float* rn = rs + (1 - cur) * FO_RS;
            #pragma unroll
            for (int q = 0; q < 16; q++) {
                int f = tid + q * 128;
                int d = f >> 6, j = f & 63;
                int fb  = (j >> 3) * 2 + (d >> 4);
                int ln  = (d & 7) * 4 + (j & 3);
                int reg = ((d >> 3) & 1) + 2 * ((j >> 2) & 1);
                vn[fb * 140 + ln * 4 + reg] = f2tf32f(pv[q]);
            }
            rn[tid]       = pr0;
            rn[tid + 128] = pr1;
        }
    }

    // epilogue: out[d][hw] = acc + v
    float* ob = out + (b * 256 + H * 32) * HW;
    #pragma unroll
    for (int ms = 0; ms < 2; ms++) {
        #pragma unroll
        for (int ns = 0; ns < 8; ns++) {
            int d0  = ms * 16 + mrow;
            int col = hw0 + wid * 64 + ns * 8 + 2 * kcol;
            float2 v0 = *(const float2*)&vbase[d0 * HW + col];
            float2 v1 = *(const float2*)&vbase[(d0 + 8) * HW + col];
            *(float2*)&ob[d0 * HW + col] =
                make_float2(acc[ms][ns][0] + v0.x, acc[ms][ns][1] + v0.y);
            *(float2*)&ob[(d0 + 8) * HW + col] =
                make_float2(acc[ms][ns][2] + v1.x, acc[ms][ns][3] + v1.y);
        }
    }
}

// ---------------------------------------------------------------------------
extern "C" void kernel_launch(void* const* d_in, const int* in_sizes, int n_in,
                              void* d_out, int out_size)
{
    const float* x = (const float*)d_in[0];
    const float* w = (const float*)d_in[1];
    if (n_in >= 2 && in_sizes[0] == 327680 && in_sizes[1] == 2097152) {
        const float* t = x; x = w; w = t;
    }
    float* out = (float*)d_out;

    static int attr_set = 0;
    if (!attr_set) {
        cudaFuncSetAttribute(proj_mma, cudaFuncAttributeMaxDynamicSharedMemorySize,
                             PJ_SMEM_BYTES);
        cudaFuncSetAttribute(row_attn4, cudaFuncAttributeMaxDynamicSharedMemorySize,
                             RA_SMEM_BYTES);
        cudaFuncSetAttribute(fused_out_mma, cudaFuncAttributeMaxDynamicSharedMemorySize,
                             FO_SMEM_BYTES);
        attr_set = 1;
    }

    dim3 g1(32, 10, 2);
    proj_mma<<<g1, 256, PJ_SMEM_BYTES>>>(x, w);

    dim3 g2r(16, 16);
    row_attn4<<<g2r, 256, RA_SMEM_BYTES>>>();
    dim3 g2c(64, 16);
    col_attn_kernel<<<g2c, 256>>>();

    dim3 g4(16, 16);
    fused_out_mma<<<g4, 128, FO_SMEM_BYTES>>>(out);
}